// round 1
// baseline (speedup 1.0000x reference)
#include <cuda_runtime.h>
#include <math.h>

#define CIN   512
#define COUT  512
#define T_IN  16
#define HWSZ  784           // 28*28
#define THW   12544         // 16*784
#define NB    2
#define NSPAT 25088         // NB*THW
#define WIDTH 28

// ---------------- scratch (device globals; no allocations allowed) ----------
__device__ float g_xbuf[NB * CIN * THW];        // conv output (relu'd)  ~51MB
__device__ float g_wt[27 * CIN * COUT];         // W transposed [tap][ci][co]
__device__ float g_p16[NB * CIN * 1  * HWSZ];
__device__ float g_p12[NB * CIN * 5  * HWSZ];
__device__ float g_p8 [NB * CIN * 9  * HWSZ];
__device__ float g_p4 [NB * CIN * 13 * HWSZ];
__device__ float g_cls[30 * NB * 13 * HWSZ];    // cls-score scratch (max T'=13)

// ---------------- W transpose: [co][ci][tap] -> [tap][ci][co] ---------------
__global__ void transpose_w(const float* __restrict__ w) {
    int idx = blockIdx.x * 256 + threadIdx.x;        // idx = (tap*512+ci)*512+co
    if (idx >= 27 * CIN * COUT) return;
    int co   = idx & 511;
    int rest = idx >> 9;
    int ci   = rest & 511;
    int tap  = rest >> 9;
    g_wt[idx] = w[(co * CIN + ci) * 27 + tap];
}

// ---------------- conv3d 3x3x3 same + bias + relu as implicit GEMM ----------
// M = cout (128/block), N = spatial (128/block), K = 27 taps x 512 cin (BK=8)
// micro-tile: 8 cout x 8 spatial, spatial packed in pairs for fma.rn.f32x2
__global__ __launch_bounds__(256, 2)
void conv_gemm(const float* __restrict__ x, const float* __restrict__ bias) {
    __shared__ __align__(16) float As[8][128];
    __shared__ __align__(16) float Bs[8][128];

    const int tid = threadIdx.x;
    const int s0  = blockIdx.x * 128;
    const int co0 = blockIdx.y * 128;
    const int ty  = tid >> 4;        // 0..15 -> cout group (8 rows each)
    const int tx  = tid & 15;        // 0..15 -> spatial group (8 cols each)

    // per-thread B-load slot coordinates (s fixed per block)
    int bB[4], tB[4], hB[4], wB[4];
#pragma unroll
    for (int i = 0; i < 4; i++) {
        int idx = tid + 256 * i;
        int sn  = idx & 127;
        int s   = s0 + sn;
        int b   = s / THW;
        int thw = s - b * THW;
        int t   = thw / HWSZ;
        int hw  = thw - t * HWSZ;
        bB[i] = b; tB[i] = t; hB[i] = hw / WIDTH; wB[i] = hw - (hw / WIDTH) * WIDTH;
    }

    unsigned long long acc[8][4];
#pragma unroll
    for (int m = 0; m < 8; m++)
#pragma unroll
        for (int j = 0; j < 4; j++) acc[m][j] = 0ull;   // (0.0f,0.0f)

    for (int tap = 0; tap < 27; tap++) {
        const int dt = tap / 9 - 1;
        const int rm = tap % 9;
        const int dh = rm / 3 - 1;
        const int dw = rm % 3 - 1;

        int ofs[4], vld[4];
#pragma unroll
        for (int i = 0; i < 4; i++) {
            int t2 = tB[i] + dt, h2 = hB[i] + dh, w2 = wB[i] + dw;
            vld[i] = ((unsigned)t2 < T_IN) && ((unsigned)h2 < 28) && ((unsigned)w2 < 28);
            ofs[i] = bB[i] * (CIN * THW) + t2 * HWSZ + h2 * WIDTH + w2;
        }
        const float* wtap = &g_wt[tap * CIN * COUT];

        for (int c0 = 0; c0 < CIN; c0 += 8) {
            // A tile: [kk][co], coalesced over co
#pragma unroll
            for (int i = 0; i < 4; i++) {
                int idx = tid + 256 * i;
                int kk = idx >> 7, cn = idx & 127;
                As[kk][cn] = wtap[(c0 + kk) * COUT + co0 + cn];
            }
            // B tile: [kk][s], gathered with tap shift
#pragma unroll
            for (int i = 0; i < 4; i++) {
                int idx = tid + 256 * i;
                int kk = idx >> 7, sn = idx & 127;
                float v = 0.f;
                if (vld[i]) v = x[ofs[i] + (c0 + kk) * THW];
                Bs[kk][sn] = v;
            }
            __syncthreads();

#pragma unroll
            for (int kk = 0; kk < 8; kk++) {
                float4 a03 = *(const float4*)&As[kk][ty * 8];
                float4 a47 = *(const float4*)&As[kk][ty * 8 + 4];
                float av[8] = {a03.x, a03.y, a03.z, a03.w, a47.x, a47.y, a47.z, a47.w};
                unsigned long long ad[8];
#pragma unroll
                for (int m = 0; m < 8; m++)
                    asm("mov.b64 %0, {%1, %1};" : "=l"(ad[m]) : "r"(__float_as_uint(av[m])));
                ulonglong2 u0 = *(const ulonglong2*)&Bs[kk][tx * 8];
                ulonglong2 u1 = *(const ulonglong2*)&Bs[kk][tx * 8 + 4];
                unsigned long long bd[4] = {u0.x, u0.y, u1.x, u1.y};
#pragma unroll
                for (int j = 0; j < 4; j++)
#pragma unroll
                    for (int m = 0; m < 8; m++)
                        asm("fma.rn.f32x2 %0, %1, %2, %0;"
                            : "+l"(acc[m][j]) : "l"(ad[m]), "l"(bd[j]));
            }
            __syncthreads();
        }
    }

    // epilogue: bias + relu, store to g_xbuf[b][co][thw]
    const int bblk = s0 / THW;            // 12544 % 128 == 0 -> whole tile same b
#pragma unroll
    for (int m = 0; m < 8; m++) {
        int co = co0 + ty * 8 + m;
        float bv = bias[co];
#pragma unroll
        for (int j = 0; j < 4; j++) {
            float2 v = *reinterpret_cast<float2*>(&acc[m][j]);
            int s   = s0 + tx * 8 + 2 * j;
            int thw = s - bblk * THW;
            float2 o2 = make_float2(fmaxf(v.x + bv, 0.f), fmaxf(v.y + bv, 0.f));
            *(float2*)&g_xbuf[bblk * (CIN * THW) + co * THW + thw] = o2;
        }
    }
}

// ---------------- temporal max pools ----------------------------------------
__global__ void pool_kernel() {
    int idx = blockIdx.x * 256 + threadIdx.x;      // (b*512+c)*784 + hw
    if (idx >= NB * CIN * HWSZ) return;
    int hw = idx % HWSZ;
    int bc = idx / HWSZ;
    const float* p = &g_xbuf[bc * THW + hw];
    float v[16];
#pragma unroll
    for (int t = 0; t < 16; t++) v[t] = p[t * HWSZ];

    float m = v[0];
#pragma unroll
    for (int t = 1; t < 16; t++) m = fmaxf(m, v[t]);
    g_p16[bc * HWSZ + hw] = m;

#pragma unroll
    for (int tp = 0; tp < 5; tp++) {
        float q = v[tp];
#pragma unroll
        for (int d = 1; d < 12; d++) q = fmaxf(q, v[tp + d]);
        g_p12[(bc * 5 + tp) * HWSZ + hw] = q;
    }
#pragma unroll
    for (int tp = 0; tp < 9; tp++) {
        float q = v[tp];
#pragma unroll
        for (int d = 1; d < 8; d++) q = fmaxf(q, v[tp + d]);
        g_p8[(bc * 9 + tp) * HWSZ + hw] = q;
    }
#pragma unroll
    for (int tp = 0; tp < 13; tp++) {
        float q = v[tp];
#pragma unroll
        for (int d = 1; d < 4; d++) q = fmaxf(q, v[tp + d]);
        g_p4[(bc * 13 + tp) * HWSZ + hw] = q;
    }
}

// ---------------- 1x1x1 head GEMM: out[o,s'] = sum_c W[o,c]*pool[c,s'] + b --
// BM=64 (o), BN=128 (s'), BK=8, 256 thr, micro 4x8. mode0 -> g_cls[o*N+s],
// mode1 -> dst[b*O*Tp784 + o*Tp784 + r]
__global__ __launch_bounds__(256)
void head_gemm(int pool_id, const float* __restrict__ Wh, const float* __restrict__ bh,
               float* __restrict__ dst, int O, int Tp, int mode) {
    const float* pool = pool_id == 0 ? g_p16 : pool_id == 1 ? g_p12
                       : pool_id == 2 ? g_p8 : g_p4;
    const int Tp784 = Tp * HWSZ;
    const int N = NB * Tp784;

    __shared__ __align__(16) float As[8][64];
    __shared__ __align__(16) float Bs[8][128];

    const int tid = threadIdx.x;
    const int s0  = blockIdx.x * 128;
    const int o0  = blockIdx.y * 64;
    const int ty  = tid >> 4;     // 0..15 -> o group (4 rows)
    const int tx  = tid & 15;     // 0..15 -> s group (8 cols)

    // A loader: 2 consecutive c for one o
    const int oL = o0 + (tid >> 2);
    const int cL = (tid & 3) * 2;

    // B loader slots
    int baseS[4], okS[4];
#pragma unroll
    for (int i = 0; i < 4; i++) {
        int idx = tid + 256 * i;
        int sn = idx & 127;
        int s = s0 + sn;
        okS[i] = s < N;
        int b = s >= Tp784 ? 1 : 0;
        int r = s - b * Tp784;
        baseS[i] = b * (CIN * Tp784) + r;
    }

    float acc[4][8];
#pragma unroll
    for (int m = 0; m < 4; m++)
#pragma unroll
        for (int j = 0; j < 8; j++) acc[m][j] = 0.f;

    for (int c0 = 0; c0 < CIN; c0 += 8) {
        float a0 = 0.f, a1 = 0.f;
        if (oL < O) {
            a0 = Wh[oL * CIN + c0 + cL];
            a1 = Wh[oL * CIN + c0 + cL + 1];
        }
        As[cL][oL - o0]     = a0;
        As[cL + 1][oL - o0] = a1;
#pragma unroll
        for (int i = 0; i < 4; i++) {
            int idx = tid + 256 * i;
            int kk = idx >> 7, sn = idx & 127;
            float v = 0.f;
            if (okS[i]) v = pool[baseS[i] + (c0 + kk) * Tp784];
            Bs[kk][sn] = v;
        }
        __syncthreads();
#pragma unroll
        for (int kk = 0; kk < 8; kk++) {
            float4 a = *(const float4*)&As[kk][ty * 4];
            float4 b0 = *(const float4*)&Bs[kk][tx * 8];
            float4 b1 = *(const float4*)&Bs[kk][tx * 8 + 4];
            float av[4] = {a.x, a.y, a.z, a.w};
            float bv[8] = {b0.x, b0.y, b0.z, b0.w, b1.x, b1.y, b1.z, b1.w};
#pragma unroll
            for (int m = 0; m < 4; m++)
#pragma unroll
                for (int j = 0; j < 8; j++) acc[m][j] += av[m] * bv[j];
        }
        __syncthreads();
    }

#pragma unroll
    for (int m = 0; m < 4; m++) {
        int o = o0 + ty * 4 + m;
        if (o >= O) continue;
        float bv = bh[o];
#pragma unroll
        for (int j = 0; j < 8; j++) {
            int s = s0 + tx * 8 + j;
            if (s >= N) continue;
            float r = acc[m][j] + bv;
            if (mode == 0) {
                g_cls[o * N + s] = r;
            } else {
                int b  = s >= Tp784 ? 1 : 0;
                int rr = s - b * Tp784;
                dst[b * O * Tp784 + o * Tp784 + rr] = r;
            }
        }
    }
}

// ---------------- paired softmax over channels (c, c+15) --------------------
__global__ void softmax_kernel(float* __restrict__ out, int Tp) {
    const int Tp784 = Tp * HWSZ;
    const int N = NB * Tp784;
    int idx = blockIdx.x * 256 + threadIdx.x;        // c*N + s, c in [0,15)
    if (idx >= 15 * N) return;
    int c = idx / N;
    int s = idx - c * N;
    float v0 = g_cls[c * N + s];
    float v1 = g_cls[(c + 15) * N + s];
    float mx = fmaxf(v0, v1);
    float e0 = expf(v0 - mx), e1 = expf(v1 - mx);
    float inv = 1.f / (e0 + e1);
    int b = s >= Tp784 ? 1 : 0;
    int r = s - b * Tp784;
    out[b * 30 * Tp784 + c * Tp784 + r]        = e0 * inv;
    out[b * 30 * Tp784 + (c + 15) * Tp784 + r] = e1 * inv;
}

// ---------------- launch -----------------------------------------------------
extern "C" void kernel_launch(void* const* d_in, const int* in_sizes, int n_in,
                              void* d_out, int out_size) {
    const float* base  = (const float*)d_in[0];
    const float* Wc    = (const float*)d_in[4];
    const float* bc    = (const float*)d_in[5];
    const float* Wcls  = (const float*)d_in[6];
    const float* bcls  = (const float*)d_in[7];
    const float* Wbb[4] = {(const float*)d_in[8],  (const float*)d_in[10],
                           (const float*)d_in[12], (const float*)d_in[14]};
    const float* bbb[4] = {(const float*)d_in[9],  (const float*)d_in[11],
                           (const float*)d_in[13], (const float*)d_in[15]};
    float* out = (float*)d_out;

    transpose_w<<<(27 * CIN * COUT + 255) / 256, 256>>>(Wc);
    conv_gemm<<<dim3(NSPAT / 128, COUT / 128), 256>>>(base, bc);
    pool_kernel<<<(NB * CIN * HWSZ + 255) / 256, 256>>>();

    const int TpA[4]   = {1, 5, 9, 13};
    const int Obb[4]   = {960, 720, 480, 240};
    // output offsets (floats): probs then bboxes, in pool order
    const long probOff[4] = {0, 47040, 282240, 705600};
    const long bboxOff[4] = {1317120, 2822400, 8467200, 15240960};

    for (int p = 0; p < 4; p++) {
        int Tp = TpA[p];
        int N = NB * Tp * HWSZ;
        int gx = (N + 127) / 128;
        // cls scores -> scratch
        head_gemm<<<dim3(gx, 1), 256>>>(p, Wcls, bcls, out, 30, Tp, 0);
        // paired softmax -> probs output
        softmax_kernel<<<(15 * N + 255) / 256, 256>>>(out + probOff[p], Tp);
        // bbox head -> direct output
        int gy = (Obb[p] + 63) / 64;
        head_gemm<<<dim3(gx, gy), 256>>>(p, Wbb[p], bbb[p], out + bboxOff[p],
                                         Obb[p], Tp, 1);
    }
}

// round 3
// speedup vs baseline: 1.9003x; 1.9003x over previous
#include <cuda_runtime.h>
#include <cuda_bf16.h>
#include <cstdint>
#include <math.h>

#define CIN   512
#define COUT  512
#define T_IN  16
#define HWSZ  784           // 28*28
#define THW   12544         // 16*784
#define NB    2
#define NSPAT 25088         // NB*THW
#define WIDTH 28

// ---------------- scratch (device globals; no allocations allowed) ----------
__device__ float g_xbuf[NB * CIN * THW];                 // conv output (relu'd)
__device__ __nv_bfloat16 g_xthi[NB * THW * CIN];          // x transposed [s][c] hi
__device__ __nv_bfloat16 g_xtlo[NB * THW * CIN];          // x transposed [s][c] lo
__device__ __nv_bfloat16 g_wthi[27 * COUT * CIN];         // W [tap][co][ci] hi
__device__ __nv_bfloat16 g_wtlo[27 * COUT * CIN];         // W [tap][co][ci] lo
__device__ float g_p16[NB * CIN * 1  * HWSZ];
__device__ float g_p12[NB * CIN * 5  * HWSZ];
__device__ float g_p8 [NB * CIN * 9  * HWSZ];
__device__ float g_p4 [NB * CIN * 13 * HWSZ];
__device__ float g_cls[30 * NB * 13 * HWSZ];

// ---------------- prep: W [co][ci][tap] -> [tap][co][ci] bf16 hi/lo ---------
__global__ void prep_w(const float* __restrict__ w) {
    int idx = blockIdx.x * 256 + threadIdx.x;
    if (idx >= 27 * COUT * CIN) return;
    int ci = idx & 511;
    int r  = idx >> 9;
    int co = r & 511;
    int tap = r >> 9;
    float v = w[(co * CIN + ci) * 27 + tap];
    __nv_bfloat16 hi = __float2bfloat16_rn(v);
    float rem = v - __bfloat162float(hi);
    g_wthi[idx] = hi;
    g_wtlo[idx] = __float2bfloat16_rn(rem);
}

// ---------------- prep: x [b][c][thw] -> [b*thw][c] bf16 hi/lo (transpose) --
__global__ void prep_x(const float* __restrict__ x) {
    __shared__ float tile[32][33];
    int b  = blockIdx.z;
    int s0 = blockIdx.x * 32;
    int c0 = blockIdx.y * 32;
    for (int i = threadIdx.y; i < 32; i += 8)
        tile[i][threadIdx.x] = x[((size_t)b * CIN + c0 + i) * THW + s0 + threadIdx.x];
    __syncthreads();
    for (int i = threadIdx.y; i < 32; i += 8) {
        float v = tile[threadIdx.x][i];
        size_t o = ((size_t)b * THW + s0 + i) * CIN + c0 + threadIdx.x;
        __nv_bfloat16 hi = __float2bfloat16_rn(v);
        float rem = v - __bfloat162float(hi);
        g_xthi[o] = hi;
        g_xtlo[o] = __float2bfloat16_rn(rem);
    }
}

// ================= mma.sync helpers =========================================
__device__ __forceinline__ uint32_t smem_u32(const void* p) {
    uint32_t a;
    asm("{ .reg .u64 t; cvta.to.shared.u64 t, %1; cvt.u32.u64 %0, t; }"
        : "=r"(a) : "l"(p));
    return a;
}
__device__ __forceinline__ void ldsm_x4(unsigned* r, uint32_t addr) {
    asm volatile("ldmatrix.sync.aligned.m8n8.x4.shared.b16 {%0,%1,%2,%3}, [%4];"
                 : "=r"(r[0]), "=r"(r[1]), "=r"(r[2]), "=r"(r[3]) : "r"(addr));
}
__device__ __forceinline__ void ldsm_x2(unsigned* r, uint32_t addr) {
    asm volatile("ldmatrix.sync.aligned.m8n8.x2.shared.b16 {%0,%1}, [%2];"
                 : "=r"(r[0]), "=r"(r[1]) : "r"(addr));
}
__device__ __forceinline__ void mma16816(float* d, const unsigned* a, const unsigned* b) {
    asm volatile(
        "mma.sync.aligned.m16n8k16.row.col.f32.bf16.bf16.f32 "
        "{%0,%1,%2,%3}, {%4,%5,%6,%7}, {%8,%9}, {%0,%1,%2,%3};"
        : "+f"(d[0]), "+f"(d[1]), "+f"(d[2]), "+f"(d[3])
        : "r"(a[0]), "r"(a[1]), "r"(a[2]), "r"(a[3]), "r"(b[0]), "r"(b[1]));
}
__device__ __forceinline__ void cp16(uint32_t saddr, const void* gaddr, int sz) {
    asm volatile("cp.async.cg.shared.global [%0], [%1], 16, %2;"
                 :: "r"(saddr), "l"(gaddr), "r"(sz) : "memory");
}
#define CP_COMMIT()  asm volatile("cp.async.commit_group;" ::: "memory")
#define CP_WAIT1()   asm volatile("cp.async.wait_group 1;" ::: "memory")

// SMEM stage layout: rows of 32 bf16 padded to 80B stride (conflict-free ldsm)
#define RSTRIDE 80
#define T_AHI 0
#define T_ALO 10240
#define T_BHI 20480
#define T_BLO 30720
#define STAGE 40960
#define NSTAGE 3
#define CONV_SMEM (STAGE * NSTAGE)
#define NKSTEP 432          // 27 taps * 16 chunks of 32 cin

// ---------------- conv3d 3x3x3 as implicit GEMM on mma.sync (bf16x3) --------
__global__ __launch_bounds__(256, 1)
void conv_mma(const float* __restrict__ bias) {
    extern __shared__ char dsm[];
    const uint32_t base = smem_u32(dsm);

    const int tid  = threadIdx.x;
    const int lane = tid & 31;
    const int wid  = tid >> 5;
    const int wm   = wid & 1;         // 0..1 -> 64 co rows
    const int wn   = wid >> 1;        // 0..3 -> 32 spatial cols
    const int s0   = blockIdx.x * 128;
    const int co0  = blockIdx.y * 128;
    const int bb   = s0 / THW;

    // ---- loader geometry: thread handles rows r0 and r0+64, 16B quarter q
    const int r0 = tid >> 2;
    const int q  = tid & 3;
    int tB[2], hB[2], wB[2];
#pragma unroll
    for (int e = 0; e < 2; e++) {
        int s   = s0 + r0 + 64 * e;
        int thw = s - bb * THW;
        int t   = thw / HWSZ;
        int hw  = thw - t * HWSZ;
        tB[e] = t; hB[e] = hw / WIDTH; wB[e] = hw - (hw / WIDTH) * WIDTH;
    }

    // issue loads for k-step j into stage j%NSTAGE
    auto issue = [&](int j) {
        const int tap = j >> 4;
        const int c0  = (j & 15) << 5;
        const int dt = tap / 9 - 1;
        const int rm = tap - (tap / 9) * 9;
        const int dh = rm / 3 - 1;
        const int dw = rm - (rm / 3) * 3 - 1;
        const uint32_t sb = base + (j % NSTAGE) * STAGE;
#pragma unroll
        for (int e = 0; e < 2; e++) {
            const int row = r0 + 64 * e;
            const uint32_t co_ = (uint32_t)(row * RSTRIDE + q * 16);
            // A (weights)
            const size_t gA = ((size_t)(tap * COUT + co0 + row)) * CIN + c0 + q * 8;
            cp16(sb + T_AHI + co_, g_wthi + gA, 16);
            cp16(sb + T_ALO + co_, g_wtlo + gA, 16);
            // B (activations, tap-shifted)
            const int t2 = tB[e] + dt, h2 = hB[e] + dh, w2 = wB[e] + dw;
            const int valid = ((unsigned)t2 < (unsigned)T_IN) &
                              ((unsigned)h2 < 28u) & ((unsigned)w2 < 28u);
            const size_t gB = valid
                ? ((size_t)bb * THW + t2 * HWSZ + h2 * WIDTH + w2) * CIN + c0 + q * 8
                : 0;
            const int sz = valid ? 16 : 0;
            cp16(sb + T_BHI + co_, g_xthi + gB, sz);
            cp16(sb + T_BLO + co_, g_xtlo + gB, sz);
        }
    };

    float acc[4][4][4];
#pragma unroll
    for (int mi = 0; mi < 4; mi++)
#pragma unroll
        for (int ni = 0; ni < 4; ni++)
#pragma unroll
            for (int r = 0; r < 4; r++) acc[mi][ni][r] = 0.f;

    issue(0); CP_COMMIT();
    issue(1); CP_COMMIT();

    // precomputed intra-warp fragment address pieces
    const uint32_t aRow = (uint32_t)((wm * 64 + (lane & 15)) * RSTRIDE);
    const uint32_t aKof = (uint32_t)(((lane >> 4) * 8) * 2);
    const uint32_t bRow = (uint32_t)((wn * 32 + (lane & 7)) * RSTRIDE);
    const uint32_t bKof = (uint32_t)((((lane >> 3) & 1) * 8) * 2);

    for (int i = 0; i < NKSTEP; i++) {
        CP_WAIT1();
        __syncthreads();
        if (i + 2 < NKSTEP) issue(i + 2);
        CP_COMMIT();

        const uint32_t sb = base + (i % NSTAGE) * STAGE;
#pragma unroll
        for (int kk = 0; kk < 2; kk++) {
            const uint32_t kByte = (uint32_t)(kk * 16 * 2);
            unsigned ah[4][4], al[4][4], bh[4][2], bl[4][2];
#pragma unroll
            for (int mi = 0; mi < 4; mi++) {
                uint32_t ad = sb + aRow + (uint32_t)(mi * 16 * RSTRIDE) + kByte + aKof;
                ldsm_x4(ah[mi], ad + T_AHI);
                ldsm_x4(al[mi], ad + T_ALO);
            }
#pragma unroll
            for (int ni = 0; ni < 4; ni++) {
                uint32_t bd = sb + bRow + (uint32_t)(ni * 8 * RSTRIDE) + kByte + bKof;
                ldsm_x2(bh[ni], bd + T_BHI);
                ldsm_x2(bl[ni], bd + T_BLO);
            }
#pragma unroll
            for (int mi = 0; mi < 4; mi++)
#pragma unroll
                for (int ni = 0; ni < 4; ni++) {
                    mma16816(acc[mi][ni], ah[mi], bh[ni]);
                    mma16816(acc[mi][ni], ah[mi], bl[ni]);
                    mma16816(acc[mi][ni], al[mi], bh[ni]);
                }
        }
    }

    // ---- epilogue: bias + relu -> g_xbuf[b][co][thw]
#pragma unroll
    for (int mi = 0; mi < 4; mi++) {
        const int row0 = co0 + wm * 64 + mi * 16 + (lane >> 2);
        const int row1 = row0 + 8;
        const float bv0 = bias[row0];
        const float bv1 = bias[row1];
#pragma unroll
        for (int ni = 0; ni < 4; ni++) {
            const int sCol = s0 + wn * 32 + ni * 8 + (lane & 3) * 2;
            const int thw  = sCol - bb * THW;
            float2 o0, o1;
            o0.x = fmaxf(acc[mi][ni][0] + bv0, 0.f);
            o0.y = fmaxf(acc[mi][ni][1] + bv0, 0.f);
            o1.x = fmaxf(acc[mi][ni][2] + bv1, 0.f);
            o1.y = fmaxf(acc[mi][ni][3] + bv1, 0.f);
            *(float2*)&g_xbuf[(size_t)bb * CIN * THW + (size_t)row0 * THW + thw] = o0;
            *(float2*)&g_xbuf[(size_t)bb * CIN * THW + (size_t)row1 * THW + thw] = o1;
        }
    }
}

// ---------------- temporal max pools ----------------------------------------
__global__ void pool_kernel() {
    int idx = blockIdx.x * 256 + threadIdx.x;
    if (idx >= NB * CIN * HWSZ) return;
    int hw = idx % HWSZ;
    int bc = idx / HWSZ;
    const float* p = &g_xbuf[(size_t)bc * THW + hw];
    float v[16];
#pragma unroll
    for (int t = 0; t < 16; t++) v[t] = p[t * HWSZ];

    float m = v[0];
#pragma unroll
    for (int t = 1; t < 16; t++) m = fmaxf(m, v[t]);
    g_p16[(size_t)bc * HWSZ + hw] = m;

#pragma unroll
    for (int tp = 0; tp < 5; tp++) {
        float qv = v[tp];
#pragma unroll
        for (int d = 1; d < 12; d++) qv = fmaxf(qv, v[tp + d]);
        g_p12[((size_t)bc * 5 + tp) * HWSZ + hw] = qv;
    }
#pragma unroll
    for (int tp = 0; tp < 9; tp++) {
        float qv = v[tp];
#pragma unroll
        for (int d = 1; d < 8; d++) qv = fmaxf(qv, v[tp + d]);
        g_p8[((size_t)bc * 9 + tp) * HWSZ + hw] = qv;
    }
#pragma unroll
    for (int tp = 0; tp < 13; tp++) {
        float qv = v[tp];
#pragma unroll
        for (int d = 1; d < 4; d++) qv = fmaxf(qv, v[tp + d]);
        g_p4[((size_t)bc * 13 + tp) * HWSZ + hw] = qv;
    }
}

// ---------------- 1x1x1 head GEMM -------------------------------------------
__global__ __launch_bounds__(256)
void head_gemm(int pool_id, const float* __restrict__ Wh, const float* __restrict__ bh,
               float* __restrict__ dst, int O, int Tp, int mode) {
    const float* pool = pool_id == 0 ? g_p16 : pool_id == 1 ? g_p12
                       : pool_id == 2 ? g_p8 : g_p4;
    const int Tp784 = Tp * HWSZ;
    const int N = NB * Tp784;

    __shared__ __align__(16) float As[8][64];
    __shared__ __align__(16) float Bs[8][128];

    const int tid = threadIdx.x;
    const int s0  = blockIdx.x * 128;
    const int o0  = blockIdx.y * 64;
    const int ty  = tid >> 4;
    const int tx  = tid & 15;

    const int oL = o0 + (tid >> 2);
    const int cL = (tid & 3) * 2;

    int baseS[4], okS[4];
#pragma unroll
    for (int i = 0; i < 4; i++) {
        int idx = tid + 256 * i;
        int sn = idx & 127;
        int ss = s0 + sn;
        okS[i] = ss < N;
        int b = ss >= Tp784 ? 1 : 0;
        int r = ss - b * Tp784;
        baseS[i] = b * (CIN * Tp784) + r;
    }

    float acc[4][8];
#pragma unroll
    for (int m = 0; m < 4; m++)
#pragma unroll
        for (int j = 0; j < 8; j++) acc[m][j] = 0.f;

    for (int c0 = 0; c0 < CIN; c0 += 8) {
        float a0 = 0.f, a1 = 0.f;
        if (oL < O) {
            a0 = Wh[oL * CIN + c0 + cL];
            a1 = Wh[oL * CIN + c0 + cL + 1];
        }
        As[cL][oL - o0]     = a0;
        As[cL + 1][oL - o0] = a1;
#pragma unroll
        for (int i = 0; i < 4; i++) {
            int idx = tid + 256 * i;
            int kk = idx >> 7, sn = idx & 127;
            float v = 0.f;
            if (okS[i]) v = pool[baseS[i] + (c0 + kk) * Tp784];
            Bs[kk][sn] = v;
        }
        __syncthreads();
#pragma unroll
        for (int kk = 0; kk < 8; kk++) {
            float4 a  = *(const float4*)&As[kk][ty * 4];
            float4 b0 = *(const float4*)&Bs[kk][tx * 8];
            float4 b1 = *(const float4*)&Bs[kk][tx * 8 + 4];
            float av[4] = {a.x, a.y, a.z, a.w};
            float bv[8] = {b0.x, b0.y, b0.z, b0.w, b1.x, b1.y, b1.z, b1.w};
#pragma unroll
            for (int m = 0; m < 4; m++)
#pragma unroll
                for (int j = 0; j < 8; j++) acc[m][j] += av[m] * bv[j];
        }
        __syncthreads();
    }

#pragma unroll
    for (int m = 0; m < 4; m++) {
        int o = o0 + ty * 4 + m;
        if (o >= O) continue;
        float bv = bh[o];
#pragma unroll
        for (int j = 0; j < 8; j++) {
            int ss = s0 + tx * 8 + j;
            if (ss >= N) continue;
            float r = acc[m][j] + bv;
            if (mode == 0) {
                g_cls[o * N + ss] = r;
            } else {
                int b  = ss >= Tp784 ? 1 : 0;
                int rr = ss - b * Tp784;
                dst[(size_t)b * O * Tp784 + (size_t)o * Tp784 + rr] = r;
            }
        }
    }
}

// ---------------- paired softmax over channels (c, c+15) --------------------
__global__ void softmax_kernel(float* __restrict__ out, int Tp) {
    const int Tp784 = Tp * HWSZ;
    const int N = NB * Tp784;
    int idx = blockIdx.x * 256 + threadIdx.x;
    if (idx >= 15 * N) return;
    int c = idx / N;
    int ss = idx - c * N;
    float v0 = g_cls[c * N + ss];
    float v1 = g_cls[(c + 15) * N + ss];
    float mx = fmaxf(v0, v1);
    float e0 = expf(v0 - mx), e1 = expf(v1 - mx);
    float inv = 1.f / (e0 + e1);
    int b = ss >= Tp784 ? 1 : 0;
    int r = ss - b * Tp784;
    out[(size_t)b * 30 * Tp784 + (size_t)c * Tp784 + r]        = e0 * inv;
    out[(size_t)b * 30 * Tp784 + (size_t)(c + 15) * Tp784 + r] = e1 * inv;
}

// ---------------- launch -----------------------------------------------------
extern "C" void kernel_launch(void* const* d_in, const int* in_sizes, int n_in,
                              void* d_out, int out_size) {
    const float* base  = (const float*)d_in[0];
    const float* Wc    = (const float*)d_in[4];
    const float* bc    = (const float*)d_in[5];
    const float* Wcls  = (const float*)d_in[6];
    const float* bcls  = (const float*)d_in[7];
    const float* Wbb[4] = {(const float*)d_in[8],  (const float*)d_in[10],
                           (const float*)d_in[12], (const float*)d_in[14]};
    const float* bbb[4] = {(const float*)d_in[9],  (const float*)d_in[11],
                           (const float*)d_in[13], (const float*)d_in[15]};
    float* out = (float*)d_out;

    cudaFuncSetAttribute(conv_mma, cudaFuncAttributeMaxDynamicSharedMemorySize,
                         CONV_SMEM);

    prep_w<<<(27 * COUT * CIN + 255) / 256, 256>>>(Wc);
    prep_x<<<dim3(THW / 32, CIN / 32, NB), dim3(32, 8)>>>(base);
    conv_mma<<<dim3(NSPAT / 128, COUT / 128), 256, CONV_SMEM>>>(bc);
    pool_kernel<<<(NB * CIN * HWSZ + 255) / 256, 256>>>();

    const int TpA[4] = {1, 5, 9, 13};
    const int Obb[4] = {960, 720, 480, 240};
    const long probOff[4] = {0, 47040, 282240, 705600};
    const long bboxOff[4] = {1317120, 2822400, 8467200, 15240960};

    for (int p = 0; p < 4; p++) {
        int Tp = TpA[p];
        int N = NB * Tp * HWSZ;
        int gx = (N + 127) / 128;
        head_gemm<<<dim3(gx, 1), 256>>>(p, Wcls, bcls, out, 30, Tp, 0);
        softmax_kernel<<<(15 * N + 255) / 256, 256>>>(out + probOff[p], Tp);
        int gy = (Obb[p] + 63) / 64;
        head_gemm<<<dim3(gx, gy), 256>>>(p, Wbb[p], bbb[p], out + bboxOff[p],
                                         Obb[p], Tp, 1);
    }
}

// round 4
// speedup vs baseline: 3.6126x; 1.9010x over previous
#include <cuda_runtime.h>
#include <cuda_bf16.h>
#include <cstdint>
#include <math.h>

#define CIN   512
#define COUT  512
#define T_IN  16
#define HWSZ  784           // 28*28
#define THW   12544         // 16*784
#define NB    2
#define WIDTH 28

#define NTILE   3136        // 2 * 8 * 14 * 14 winograd tiles
#define NTPAD   3200        // padded to 25 * 128
#define TPB     1568        // tiles per batch
#define NPTS    64          // 4*4*4 transform points

// ---------------- scratch (device globals; no allocations allowed) ----------
__device__ float g_xbuf[NB * CIN * THW];               // conv output (relu'd)
__device__ float g_xt[NB * THW * CIN];                 // x transposed [s][c] fp32
__device__ __nv_bfloat16 g_uhi[NPTS * COUT * CIN];     // weights  [p][co][ci]
__device__ __nv_bfloat16 g_ulo[NPTS * COUT * CIN];
__device__ __nv_bfloat16 g_vhi[(size_t)NPTS * NTPAD * CIN];  // acts [p][n][ci]
__device__ __nv_bfloat16 g_vlo[(size_t)NPTS * NTPAD * CIN];
__device__ float g_m[(size_t)NPTS * COUT * NTPAD];     // gemm out [p][co][n]
__device__ float g_p16[NB * CIN * 1  * HWSZ];
__device__ float g_p12[NB * CIN * 5  * HWSZ];
__device__ float g_p8 [NB * CIN * 9  * HWSZ];
__device__ float g_p4 [NB * CIN * 13 * HWSZ];
__device__ float g_cls[30 * NB * 13 * HWSZ];

// ---------------- weight transform: [co][ci][27] -> U[p][co][ci] hi/lo ------
__global__ void wino_w(const float* __restrict__ w) {
    int idx = blockIdx.x * 256 + threadIdx.x;
    if (idx >= COUT * CIN) return;
    int ci = idx & 511;
    int co = idx >> 9;
    float g[27];
#pragma unroll
    for (int k = 0; k < 27; k++) g[k] = w[(size_t)idx * 27 + k];

    float u1[4][9];
#pragma unroll
    for (int i = 0; i < 9; i++) {
        float c0 = g[i], c1 = g[9 + i], c2 = g[18 + i];
        u1[0][i] = c0;
        u1[1][i] = 0.5f * (c0 + c1 + c2);
        u1[2][i] = 0.5f * (c0 - c1 + c2);
        u1[3][i] = c2;
    }
    float u2[4][4][3];
#pragma unroll
    for (int a = 0; a < 4; a++)
#pragma unroll
        for (int kw = 0; kw < 3; kw++) {
            float c0 = u1[a][kw], c1 = u1[a][3 + kw], c2 = u1[a][6 + kw];
            u2[a][0][kw] = c0;
            u2[a][1][kw] = 0.5f * (c0 + c1 + c2);
            u2[a][2][kw] = 0.5f * (c0 - c1 + c2);
            u2[a][3][kw] = c2;
        }
#pragma unroll
    for (int a = 0; a < 4; a++)
#pragma unroll
        for (int bh = 0; bh < 4; bh++) {
            float c0 = u2[a][bh][0], c1 = u2[a][bh][1], c2 = u2[a][bh][2];
            float uw[4];
            uw[0] = c0;
            uw[1] = 0.5f * (c0 + c1 + c2);
            uw[2] = 0.5f * (c0 - c1 + c2);
            uw[3] = c2;
#pragma unroll
            for (int cw = 0; cw < 4; cw++) {
                int p = a * 16 + bh * 4 + cw;
                float v = uw[cw];
                __nv_bfloat16 hi = __float2bfloat16_rn(v);
                float rem = v - __bfloat162float(hi);
                size_t o = ((size_t)p * COUT + co) * CIN + ci;
                g_uhi[o] = hi;
                g_ulo[o] = __float2bfloat16_rn(rem);
            }
        }
}

// ---------------- x [b][c][thw] -> [b*thw][c] fp32 transpose ----------------
__global__ void prep_xt(const float* __restrict__ x) {
    __shared__ float tile[32][33];
    int b  = blockIdx.z;
    int s0 = blockIdx.x * 32;
    int c0 = blockIdx.y * 32;
    for (int i = threadIdx.y; i < 32; i += 8)
        tile[i][threadIdx.x] = x[((size_t)b * CIN + c0 + i) * THW + s0 + threadIdx.x];
    __syncthreads();
    for (int i = threadIdx.y; i < 32; i += 8)
        g_xt[((size_t)b * THW + s0 + i) * CIN + c0 + threadIdx.x] = tile[threadIdx.x][i];
}

// ---------------- input transform: V[p][n][ci] hi/lo ------------------------
__global__ __launch_bounds__(256, 1)
void wino_x() {
    const int n  = blockIdx.x;
    const int ci = blockIdx.y * 256 + threadIdx.x;
    float d[64];
    if (n < NTILE) {
        int b  = n / TPB;
        int r  = n - b * TPB;
        int tT = r / 196;
        int r2 = r - tT * 196;
        int tH = r2 / 14;
        int tW = r2 - tH * 14;
        int t0 = 2 * tT - 1, h0 = 2 * tH - 1, w0 = 2 * tW - 1;
#pragma unroll
        for (int dt = 0; dt < 4; dt++) {
            int t = t0 + dt;
#pragma unroll
            for (int dh = 0; dh < 4; dh++) {
                int h = h0 + dh;
#pragma unroll
                for (int dw = 0; dw < 4; dw++) {
                    int w = w0 + dw;
                    int ok = ((unsigned)t < (unsigned)T_IN) & ((unsigned)h < 28u) &
                             ((unsigned)w < 28u);
                    float v = 0.f;
                    if (ok)
                        v = g_xt[((size_t)b * THW + t * HWSZ + h * WIDTH + w) * CIN + ci];
                    d[dt * 16 + dh * 4 + dw] = v;
                }
            }
        }
    } else {
#pragma unroll
        for (int k = 0; k < 64; k++) d[k] = 0.f;
    }
    // B^T along w
#pragma unroll
    for (int i = 0; i < 16; i++) {
        float a0 = d[i * 4 + 0], a1 = d[i * 4 + 1], a2 = d[i * 4 + 2], a3 = d[i * 4 + 3];
        d[i * 4 + 0] = a0 - a2;
        d[i * 4 + 1] = a1 + a2;
        d[i * 4 + 2] = a2 - a1;
        d[i * 4 + 3] = a1 - a3;
    }
    // B^T along h
#pragma unroll
    for (int dt = 0; dt < 4; dt++)
#pragma unroll
        for (int dw = 0; dw < 4; dw++) {
            int i0 = dt * 16 + dw;
            float a0 = d[i0], a1 = d[i0 + 4], a2 = d[i0 + 8], a3 = d[i0 + 12];
            d[i0]      = a0 - a2;
            d[i0 + 4]  = a1 + a2;
            d[i0 + 8]  = a2 - a1;
            d[i0 + 12] = a1 - a3;
        }
    // B^T along t
#pragma unroll
    for (int i = 0; i < 16; i++) {
        float a0 = d[i], a1 = d[i + 16], a2 = d[i + 32], a3 = d[i + 48];
        d[i]      = a0 - a2;
        d[i + 16] = a1 + a2;
        d[i + 32] = a2 - a1;
        d[i + 48] = a1 - a3;
    }
    size_t o = ((size_t)n) * CIN + ci;
    const size_t stride = (size_t)NTPAD * CIN;
#pragma unroll
    for (int p = 0; p < 64; p++) {
        float v = d[p];
        __nv_bfloat16 hi = __float2bfloat16_rn(v);
        float rem = v - __bfloat162float(hi);
        g_vhi[o] = hi;
        g_vlo[o] = __float2bfloat16_rn(rem);
        o += stride;
    }
}

// ================= mma.sync helpers =========================================
__device__ __forceinline__ uint32_t smem_u32(const void* p) {
    uint32_t a;
    asm("{ .reg .u64 t; cvta.to.shared.u64 t, %1; cvt.u32.u64 %0, t; }"
        : "=r"(a) : "l"(p));
    return a;
}
__device__ __forceinline__ void ldsm_x4(unsigned* r, uint32_t addr) {
    asm volatile("ldmatrix.sync.aligned.m8n8.x4.shared.b16 {%0,%1,%2,%3}, [%4];"
                 : "=r"(r[0]), "=r"(r[1]), "=r"(r[2]), "=r"(r[3]) : "r"(addr));
}
__device__ __forceinline__ void ldsm_x2(unsigned* r, uint32_t addr) {
    asm volatile("ldmatrix.sync.aligned.m8n8.x2.shared.b16 {%0,%1}, [%2];"
                 : "=r"(r[0]), "=r"(r[1]) : "r"(addr));
}
__device__ __forceinline__ void mma16816(float* d, const unsigned* a, const unsigned* b) {
    asm volatile(
        "mma.sync.aligned.m16n8k16.row.col.f32.bf16.bf16.f32 "
        "{%0,%1,%2,%3}, {%4,%5,%6,%7}, {%8,%9}, {%0,%1,%2,%3};"
        : "+f"(d[0]), "+f"(d[1]), "+f"(d[2]), "+f"(d[3])
        : "r"(a[0]), "r"(a[1]), "r"(a[2]), "r"(a[3]), "r"(b[0]), "r"(b[1]));
}
__device__ __forceinline__ void cp16(uint32_t saddr, const void* gaddr) {
    asm volatile("cp.async.cg.shared.global [%0], [%1], 16;"
                 :: "r"(saddr), "l"(gaddr) : "memory");
}
#define CP_COMMIT()  asm volatile("cp.async.commit_group;" ::: "memory")
#define CP_WAIT1()   asm volatile("cp.async.wait_group 1;" ::: "memory")

#define RSTRIDE 80
#define T_AHI 0
#define T_ALO 10240
#define T_BHI 20480
#define T_BLO 30720
#define STAGE 40960
#define NSTAGE 3
#define CONV_SMEM (STAGE * NSTAGE)
#define NKSTEP 16           // K = 512 in chunks of 32

// ---------------- winograd-domain GEMM (bf16x3 mma.sync) --------------------
// grid (25 n-blocks, 4 co-blocks, 64 points), block 256
__global__ __launch_bounds__(256, 1)
void wino_gemm() {
    extern __shared__ char dsm[];
    const uint32_t base = smem_u32(dsm);

    const int tid  = threadIdx.x;
    const int lane = tid & 31;
    const int wid  = tid >> 5;
    const int wm   = wid & 1;
    const int wn   = wid >> 1;
    const int n0   = blockIdx.x * 128;
    const int co0  = blockIdx.y * 128;
    const int p    = blockIdx.z;

    const int r0 = tid >> 2;
    const int q  = tid & 3;

    auto issue = [&](int j) {
        const int c0 = j << 5;
        const uint32_t sb = base + (j % NSTAGE) * STAGE;
#pragma unroll
        for (int e = 0; e < 2; e++) {
            const int row = r0 + 64 * e;
            const uint32_t co_ = (uint32_t)(row * RSTRIDE + q * 16);
            const size_t gA = ((size_t)p * COUT + co0 + row) * CIN + c0 + q * 8;
            cp16(sb + T_AHI + co_, g_uhi + gA);
            cp16(sb + T_ALO + co_, g_ulo + gA);
            const size_t gB = ((size_t)p * NTPAD + n0 + row) * CIN + c0 + q * 8;
            cp16(sb + T_BHI + co_, g_vhi + gB);
            cp16(sb + T_BLO + co_, g_vlo + gB);
        }
    };

    float acc[4][4][4];
#pragma unroll
    for (int mi = 0; mi < 4; mi++)
#pragma unroll
        for (int ni = 0; ni < 4; ni++)
#pragma unroll
            for (int r = 0; r < 4; r++) acc[mi][ni][r] = 0.f;

    issue(0); CP_COMMIT();
    issue(1); CP_COMMIT();

    const uint32_t aRow = (uint32_t)((wm * 64 + (lane & 15)) * RSTRIDE);
    const uint32_t aKof = (uint32_t)(((lane >> 4) * 8) * 2);
    const uint32_t bRow = (uint32_t)((wn * 32 + (lane & 7)) * RSTRIDE);
    const uint32_t bKof = (uint32_t)((((lane >> 3) & 1) * 8) * 2);

    for (int i = 0; i < NKSTEP; i++) {
        CP_WAIT1();
        __syncthreads();
        if (i + 2 < NKSTEP) issue(i + 2);
        CP_COMMIT();

        const uint32_t sb = base + (i % NSTAGE) * STAGE;
#pragma unroll
        for (int kk = 0; kk < 2; kk++) {
            const uint32_t kByte = (uint32_t)(kk * 16 * 2);
            unsigned ah[4][4], al[4][4], bh[4][2], bl[4][2];
#pragma unroll
            for (int mi = 0; mi < 4; mi++) {
                uint32_t ad = sb + aRow + (uint32_t)(mi * 16 * RSTRIDE) + kByte + aKof;
                ldsm_x4(ah[mi], ad + T_AHI);
                ldsm_x4(al[mi], ad + T_ALO);
            }
#pragma unroll
            for (int ni = 0; ni < 4; ni++) {
                uint32_t bd = sb + bRow + (uint32_t)(ni * 8 * RSTRIDE) + kByte + bKof;
                ldsm_x2(bh[ni], bd + T_BHI);
                ldsm_x2(bl[ni], bd + T_BLO);
            }
#pragma unroll
            for (int mi = 0; mi < 4; mi++)
#pragma unroll
                for (int ni = 0; ni < 4; ni++) {
                    mma16816(acc[mi][ni], ah[mi], bh[ni]);
                    mma16816(acc[mi][ni], ah[mi], bl[ni]);
                    mma16816(acc[mi][ni], al[mi], bh[ni]);
                }
        }
    }

    // epilogue: raw fp32 -> g_m[p][co][n]
#pragma unroll
    for (int mi = 0; mi < 4; mi++) {
        const int row0 = co0 + wm * 64 + mi * 16 + (lane >> 2);
        const int row1 = row0 + 8;
#pragma unroll
        for (int ni = 0; ni < 4; ni++) {
            const int col = n0 + wn * 32 + ni * 8 + (lane & 3) * 2;
            float2 o0 = make_float2(acc[mi][ni][0], acc[mi][ni][1]);
            float2 o1 = make_float2(acc[mi][ni][2], acc[mi][ni][3]);
            *(float2*)&g_m[((size_t)p * COUT + row0) * NTPAD + col] = o0;
            *(float2*)&g_m[((size_t)p * COUT + row1) * NTPAD + col] = o1;
        }
    }
}

// ---------------- inverse transform + bias + relu ---------------------------
// grid (98, 64), block 256: warp -> co, lane -> n
__global__ __launch_bounds__(256, 1)
void wino_out(const float* __restrict__ bias) {
    const int lane = threadIdx.x & 31;
    const int n  = blockIdx.x * 32 + lane;
    const int co = blockIdx.y * 8 + (threadIdx.x >> 5);

    float m[64];
    {
        size_t o = (size_t)co * NTPAD + n;
        const size_t stride = (size_t)COUT * NTPAD;
#pragma unroll
        for (int pp = 0; pp < 64; pp++) {
            m[pp] = g_m[o];
            o += stride;
        }
    }
    // A^T along t: 64 -> 32
    float z[32];
#pragma unroll
    for (int i = 0; i < 16; i++) {
        float m0 = m[i], m1 = m[16 + i], m2 = m[32 + i], m3 = m[48 + i];
        z[i]      = m0 + m1 + m2;
        z[16 + i] = m1 - m2 - m3;
    }
    // A^T along h: 32 -> 16
    float y2[16];
#pragma unroll
    for (int a = 0; a < 2; a++)
#pragma unroll
        for (int dw = 0; dw < 4; dw++) {
            int i0 = a * 16 + dw;
            float m0 = z[i0], m1 = z[i0 + 4], m2 = z[i0 + 8], m3 = z[i0 + 12];
            y2[a * 8 + dw]     = m0 + m1 + m2;
            y2[a * 8 + 4 + dw] = m1 - m2 - m3;
        }
    // A^T along w: 16 -> 8
    float out[8];
#pragma unroll
    for (int a = 0; a < 2; a++)
#pragma unroll
        for (int b2 = 0; b2 < 2; b2++) {
            int i0 = a * 8 + b2 * 4;
            out[a * 4 + b2 * 2 + 0] = y2[i0] + y2[i0 + 1] + y2[i0 + 2];
            out[a * 4 + b2 * 2 + 1] = y2[i0 + 1] - y2[i0 + 2] - y2[i0 + 3];
        }

    const float bv = bias[co];
    int b  = n / TPB;
    int r  = n - b * TPB;
    int tT = r / 196;
    int r2 = r - tT * 196;
    int tH = r2 / 14;
    int tW = r2 - tH * 14;
    int t = 2 * tT, h = 2 * tH, w = 2 * tW;
    float* dst = g_xbuf + ((size_t)b * CIN + co) * THW;
#pragma unroll
    for (int dt = 0; dt < 2; dt++)
#pragma unroll
        for (int dh = 0; dh < 2; dh++) {
            float2 v;
            v.x = fmaxf(out[dt * 4 + dh * 2 + 0] + bv, 0.f);
            v.y = fmaxf(out[dt * 4 + dh * 2 + 1] + bv, 0.f);
            *(float2*)&dst[(t + dt) * HWSZ + (h + dh) * WIDTH + w] = v;
        }
}

// ---------------- temporal max pools ----------------------------------------
__global__ void pool_kernel() {
    int idx = blockIdx.x * 256 + threadIdx.x;
    if (idx >= NB * CIN * HWSZ) return;
    int hw = idx % HWSZ;
    int bc = idx / HWSZ;
    const float* p = &g_xbuf[(size_t)bc * THW + hw];
    float v[16];
#pragma unroll
    for (int t = 0; t < 16; t++) v[t] = p[t * HWSZ];

    float m = v[0];
#pragma unroll
    for (int t = 1; t < 16; t++) m = fmaxf(m, v[t]);
    g_p16[(size_t)bc * HWSZ + hw] = m;

#pragma unroll
    for (int tp = 0; tp < 5; tp++) {
        float qv = v[tp];
#pragma unroll
        for (int d = 1; d < 12; d++) qv = fmaxf(qv, v[tp + d]);
        g_p12[((size_t)bc * 5 + tp) * HWSZ + hw] = qv;
    }
#pragma unroll
    for (int tp = 0; tp < 9; tp++) {
        float qv = v[tp];
#pragma unroll
        for (int d = 1; d < 8; d++) qv = fmaxf(qv, v[tp + d]);
        g_p8[((size_t)bc * 9 + tp) * HWSZ + hw] = qv;
    }
#pragma unroll
    for (int tp = 0; tp < 13; tp++) {
        float qv = v[tp];
#pragma unroll
        for (int d = 1; d < 4; d++) qv = fmaxf(qv, v[tp + d]);
        g_p4[((size_t)bc * 13 + tp) * HWSZ + hw] = qv;
    }
}

// ---------------- 1x1x1 head GEMM (packed f32x2) ----------------------------
__global__ __launch_bounds__(256)
void head_gemm(int pool_id, const float* __restrict__ Wh, const float* __restrict__ bh,
               float* __restrict__ dst, int O, int Tp, int mode) {
    const float* pool = pool_id == 0 ? g_p16 : pool_id == 1 ? g_p12
                       : pool_id == 2 ? g_p8 : g_p4;
    const int Tp784 = Tp * HWSZ;
    const int N = NB * Tp784;

    __shared__ __align__(16) float As[8][64];
    __shared__ __align__(16) float Bs[8][128];

    const int tid = threadIdx.x;
    const int s0  = blockIdx.x * 128;
    const int o0  = blockIdx.y * 64;
    const int ty  = tid >> 4;
    const int tx  = tid & 15;

    const int oL = o0 + (tid >> 2);
    const int cL = (tid & 3) * 2;

    int baseS[4], okS[4];
#pragma unroll
    for (int i = 0; i < 4; i++) {
        int idx = tid + 256 * i;
        int sn = idx & 127;
        int ss = s0 + sn;
        okS[i] = ss < N;
        int b = ss >= Tp784 ? 1 : 0;
        int r = ss - b * Tp784;
        baseS[i] = b * (CIN * Tp784) + r;
    }

    unsigned long long acc2[4][4];
#pragma unroll
    for (int m = 0; m < 4; m++)
#pragma unroll
        for (int j = 0; j < 4; j++) acc2[m][j] = 0ull;

    for (int c0 = 0; c0 < CIN; c0 += 8) {
        float a0 = 0.f, a1 = 0.f;
        if (oL < O) {
            a0 = Wh[oL * CIN + c0 + cL];
            a1 = Wh[oL * CIN + c0 + cL + 1];
        }
        As[cL][oL - o0]     = a0;
        As[cL + 1][oL - o0] = a1;
#pragma unroll
        for (int i = 0; i < 4; i++) {
            int idx = tid + 256 * i;
            int kk = idx >> 7, sn = idx & 127;
            float v = 0.f;
            if (okS[i]) v = pool[baseS[i] + (c0 + kk) * Tp784];
            Bs[kk][sn] = v;
        }
        __syncthreads();
#pragma unroll
        for (int kk = 0; kk < 8; kk++) {
            float4 a = *(const float4*)&As[kk][ty * 4];
            float av[4] = {a.x, a.y, a.z, a.w};
            ulonglong2 u0 = *(const ulonglong2*)&Bs[kk][tx * 8];
            ulonglong2 u1 = *(const ulonglong2*)&Bs[kk][tx * 8 + 4];
            unsigned long long bd[4] = {u0.x, u0.y, u1.x, u1.y};
#pragma unroll
            for (int m = 0; m < 4; m++) {
                unsigned long long ad;
                asm("mov.b64 %0, {%1, %1};" : "=l"(ad) : "r"(__float_as_uint(av[m])));
#pragma unroll
                for (int j = 0; j < 4; j++)
                    asm("fma.rn.f32x2 %0, %1, %2, %0;"
                        : "+l"(acc2[m][j]) : "l"(ad), "l"(bd[j]));
            }
        }
        __syncthreads();
    }

#pragma unroll
    for (int m = 0; m < 4; m++) {
        int o = o0 + ty * 4 + m;
        if (o >= O) continue;
        float bv = bh[o];
#pragma unroll
        for (int j = 0; j < 4; j++) {
            float2 v = *reinterpret_cast<float2*>(&acc2[m][j]);
#pragma unroll
            for (int e = 0; e < 2; e++) {
                int ss = s0 + tx * 8 + 2 * j + e;
                if (ss >= N) continue;
                float r = (e ? v.y : v.x) + bv;
                if (mode == 0) {
                    g_cls[o * N + ss] = r;
                } else {
                    int b  = ss >= Tp784 ? 1 : 0;
                    int rr = ss - b * Tp784;
                    dst[(size_t)b * O * Tp784 + (size_t)o * Tp784 + rr] = r;
                }
            }
        }
    }
}

// ---------------- paired softmax over channels (c, c+15) --------------------
__global__ void softmax_kernel(float* __restrict__ out, int Tp) {
    const int Tp784 = Tp * HWSZ;
    const int N = NB * Tp784;
    int idx = blockIdx.x * 256 + threadIdx.x;
    if (idx >= 15 * N) return;
    int c = idx / N;
    int ss = idx - c * N;
    float v0 = g_cls[c * N + ss];
    float v1 = g_cls[(c + 15) * N + ss];
    float mx = fmaxf(v0, v1);
    float e0 = expf(v0 - mx), e1 = expf(v1 - mx);
    float inv = 1.f / (e0 + e1);
    int b = ss >= Tp784 ? 1 : 0;
    int r = ss - b * Tp784;
    out[(size_t)b * 30 * Tp784 + (size_t)c * Tp784 + r]        = e0 * inv;
    out[(size_t)b * 30 * Tp784 + (size_t)(c + 15) * Tp784 + r] = e1 * inv;
}

// ---------------- launch -----------------------------------------------------
extern "C" void kernel_launch(void* const* d_in, const int* in_sizes, int n_in,
                              void* d_out, int out_size) {
    const float* base  = (const float*)d_in[0];
    const float* Wc    = (const float*)d_in[4];
    const float* bc    = (const float*)d_in[5];
    const float* Wcls  = (const float*)d_in[6];
    const float* bcls  = (const float*)d_in[7];
    const float* Wbb[4] = {(const float*)d_in[8],  (const float*)d_in[10],
                           (const float*)d_in[12], (const float*)d_in[14]};
    const float* bbb[4] = {(const float*)d_in[9],  (const float*)d_in[11],
                           (const float*)d_in[13], (const float*)d_in[15]};
    float* out = (float*)d_out;

    cudaFuncSetAttribute(wino_gemm, cudaFuncAttributeMaxDynamicSharedMemorySize,
                         CONV_SMEM);

    wino_w<<<(COUT * CIN + 255) / 256, 256>>>(Wc);
    prep_xt<<<dim3(THW / 32, CIN / 32, NB), dim3(32, 8)>>>(base);
    wino_x<<<dim3(NTPAD, 2), 256>>>();
    wino_gemm<<<dim3(NTPAD / 128, COUT / 128, NPTS), 256, CONV_SMEM>>>();
    wino_out<<<dim3(NTILE / 32, COUT / 8), 256>>>(bc);
    pool_kernel<<<(NB * CIN * HWSZ + 255) / 256, 256>>>();

    const int TpA[4] = {1, 5, 9, 13};
    const int Obb[4] = {960, 720, 480, 240};
    const long probOff[4] = {0, 47040, 282240, 705600};
    const long bboxOff[4] = {1317120, 2822400, 8467200, 15240960};

    for (int p = 0; p < 4; p++) {
        int Tp = TpA[p];
        int N = NB * Tp * HWSZ;
        int gx = (N + 127) / 128;
        head_gemm<<<dim3(gx, 1), 256>>>(p, Wcls, bcls, out, 30, Tp, 0);
        softmax_kernel<<<(15 * N + 255) / 256, 256>>>(out + probOff[p], Tp);
        int gy = (Obb[p] + 63) / 64;
        head_gemm<<<dim3(gx, gy), 256>>>(p, Wbb[p], bbb[p], out + bboxOff[p],
                                         Obb[p], Tp, 1);
    }
}

// round 5
// speedup vs baseline: 3.8989x; 1.0793x over previous
#include <cuda_runtime.h>
#include <cuda_bf16.h>
#include <cstdint>
#include <math.h>

#define CIN   512
#define COUT  512
#define T_IN  16
#define HWSZ  784           // 28*28
#define THW   12544         // 16*784
#define NB    2
#define WIDTH 28

#define NTILE   3136        // 2 * 8 * 14 * 14 winograd tiles
#define NTPAD   3200        // padded to 25 * 128
#define TPB     1568        // tiles per batch
#define NPTS    64          // 4*4*4 transform points

// ---------------- scratch (device globals; no allocations allowed) ----------
__device__ float g_xbuf[NB * CIN * THW];               // conv output (relu'd)
__device__ float g_xt[NB * THW * CIN];                 // x transposed [s][c] fp32
__device__ __nv_bfloat16 g_uhi[NPTS * COUT * CIN];     // weights  [p][co][ci]
__device__ __nv_bfloat16 g_ulo[NPTS * COUT * CIN];
__device__ __nv_bfloat16 g_vhi[(size_t)NPTS * NTPAD * CIN];  // acts [p][n][ci]
__device__ __nv_bfloat16 g_vlo[(size_t)NPTS * NTPAD * CIN];
__device__ float g_m[(size_t)NPTS * COUT * NTPAD];     // gemm out [p][co][n]
__device__ float g_p16[NB * CIN * 1  * HWSZ];
__device__ float g_p12[NB * CIN * 5  * HWSZ];
__device__ float g_p8 [NB * CIN * 9  * HWSZ];
__device__ float g_p4 [NB * CIN * 13 * HWSZ];
__device__ float g_cls[30 * NB * 13 * HWSZ];

// ---------------- weight transform: [co][ci][27] -> U[p][co][ci] hi/lo ------
__global__ void wino_w(const float* __restrict__ w) {
    int idx = blockIdx.x * 256 + threadIdx.x;
    if (idx >= COUT * CIN) return;
    int ci = idx & 511;
    int co = idx >> 9;
    float g[27];
#pragma unroll
    for (int k = 0; k < 27; k++) g[k] = w[(size_t)idx * 27 + k];

    float u1[4][9];
#pragma unroll
    for (int i = 0; i < 9; i++) {
        float c0 = g[i], c1 = g[9 + i], c2 = g[18 + i];
        u1[0][i] = c0;
        u1[1][i] = 0.5f * (c0 + c1 + c2);
        u1[2][i] = 0.5f * (c0 - c1 + c2);
        u1[3][i] = c2;
    }
    float u2[4][4][3];
#pragma unroll
    for (int a = 0; a < 4; a++)
#pragma unroll
        for (int kw = 0; kw < 3; kw++) {
            float c0 = u1[a][kw], c1 = u1[a][3 + kw], c2 = u1[a][6 + kw];
            u2[a][0][kw] = c0;
            u2[a][1][kw] = 0.5f * (c0 + c1 + c2);
            u2[a][2][kw] = 0.5f * (c0 - c1 + c2);
            u2[a][3][kw] = c2;
        }
#pragma unroll
    for (int a = 0; a < 4; a++)
#pragma unroll
        for (int bh = 0; bh < 4; bh++) {
            float c0 = u2[a][bh][0], c1 = u2[a][bh][1], c2 = u2[a][bh][2];
            float uw[4];
            uw[0] = c0;
            uw[1] = 0.5f * (c0 + c1 + c2);
            uw[2] = 0.5f * (c0 - c1 + c2);
            uw[3] = c2;
#pragma unroll
            for (int cw = 0; cw < 4; cw++) {
                int p = a * 16 + bh * 4 + cw;
                float v = uw[cw];
                __nv_bfloat16 hi = __float2bfloat16_rn(v);
                float rem = v - __bfloat162float(hi);
                size_t o = ((size_t)p * COUT + co) * CIN + ci;
                g_uhi[o] = hi;
                g_ulo[o] = __float2bfloat16_rn(rem);
            }
        }
}

// ---------------- x [b][c][thw] -> [b*thw][c] fp32 transpose ----------------
__global__ void prep_xt(const float* __restrict__ x) {
    __shared__ float tile[32][33];
    int b  = blockIdx.z;
    int s0 = blockIdx.x * 32;
    int c0 = blockIdx.y * 32;
    for (int i = threadIdx.y; i < 32; i += 8)
        tile[i][threadIdx.x] = x[((size_t)b * CIN + c0 + i) * THW + s0 + threadIdx.x];
    __syncthreads();
    for (int i = threadIdx.y; i < 32; i += 8)
        g_xt[((size_t)b * THW + s0 + i) * CIN + c0 + threadIdx.x] = tile[threadIdx.x][i];
}

// ---------------- input transform: V[p][n][ci] hi/lo ------------------------
__global__ __launch_bounds__(256, 1)
void wino_x() {
    const int n  = blockIdx.x;
    const int ci = blockIdx.y * 256 + threadIdx.x;
    float d[64];
    if (n < NTILE) {
        int b  = n / TPB;
        int r  = n - b * TPB;
        int tT = r / 196;
        int r2 = r - tT * 196;
        int tH = r2 / 14;
        int tW = r2 - tH * 14;
        int t0 = 2 * tT - 1, h0 = 2 * tH - 1, w0 = 2 * tW - 1;
#pragma unroll
        for (int dt = 0; dt < 4; dt++) {
            int t = t0 + dt;
#pragma unroll
            for (int dh = 0; dh < 4; dh++) {
                int h = h0 + dh;
#pragma unroll
                for (int dw = 0; dw < 4; dw++) {
                    int w = w0 + dw;
                    int ok = ((unsigned)t < (unsigned)T_IN) & ((unsigned)h < 28u) &
                             ((unsigned)w < 28u);
                    float v = 0.f;
                    if (ok)
                        v = g_xt[((size_t)b * THW + t * HWSZ + h * WIDTH + w) * CIN + ci];
                    d[dt * 16 + dh * 4 + dw] = v;
                }
            }
        }
    } else {
#pragma unroll
        for (int k = 0; k < 64; k++) d[k] = 0.f;
    }
    // B^T along w
#pragma unroll
    for (int i = 0; i < 16; i++) {
        float a0 = d[i * 4 + 0], a1 = d[i * 4 + 1], a2 = d[i * 4 + 2], a3 = d[i * 4 + 3];
        d[i * 4 + 0] = a0 - a2;
        d[i * 4 + 1] = a1 + a2;
        d[i * 4 + 2] = a2 - a1;
        d[i * 4 + 3] = a1 - a3;
    }
    // B^T along h
#pragma unroll
    for (int dt = 0; dt < 4; dt++)
#pragma unroll
        for (int dw = 0; dw < 4; dw++) {
            int i0 = dt * 16 + dw;
            float a0 = d[i0], a1 = d[i0 + 4], a2 = d[i0 + 8], a3 = d[i0 + 12];
            d[i0]      = a0 - a2;
            d[i0 + 4]  = a1 + a2;
            d[i0 + 8]  = a2 - a1;
            d[i0 + 12] = a1 - a3;
        }
    // B^T along t
#pragma unroll
    for (int i = 0; i < 16; i++) {
        float a0 = d[i], a1 = d[i + 16], a2 = d[i + 32], a3 = d[i + 48];
        d[i]      = a0 - a2;
        d[i + 16] = a1 + a2;
        d[i + 32] = a2 - a1;
        d[i + 48] = a1 - a3;
    }
    size_t o = ((size_t)n) * CIN + ci;
    const size_t stride = (size_t)NTPAD * CIN;
#pragma unroll
    for (int p = 0; p < 64; p++) {
        float v = d[p];
        __nv_bfloat16 hi = __float2bfloat16_rn(v);
        float rem = v - __bfloat162float(hi);
        g_vhi[o] = hi;
        g_vlo[o] = __float2bfloat16_rn(rem);
        o += stride;
    }
}

// ================= mma.sync helpers =========================================
__device__ __forceinline__ uint32_t smem_u32(const void* p) {
    uint32_t a;
    asm("{ .reg .u64 t; cvta.to.shared.u64 t, %1; cvt.u32.u64 %0, t; }"
        : "=r"(a) : "l"(p));
    return a;
}
__device__ __forceinline__ void ldsm_x4(unsigned* r, uint32_t addr) {
    asm volatile("ldmatrix.sync.aligned.m8n8.x4.shared.b16 {%0,%1,%2,%3}, [%4];"
                 : "=r"(r[0]), "=r"(r[1]), "=r"(r[2]), "=r"(r[3]) : "r"(addr));
}
__device__ __forceinline__ void mma16816(float* d, const unsigned* a, const unsigned* b) {
    asm volatile(
        "mma.sync.aligned.m16n8k16.row.col.f32.bf16.bf16.f32 "
        "{%0,%1,%2,%3}, {%4,%5,%6,%7}, {%8,%9}, {%0,%1,%2,%3};"
        : "+f"(d[0]), "+f"(d[1]), "+f"(d[2]), "+f"(d[3])
        : "r"(a[0]), "r"(a[1]), "r"(a[2]), "r"(a[3]), "r"(b[0]), "r"(b[1]));
}
__device__ __forceinline__ void cp16(uint32_t saddr, const void* gaddr) {
    asm volatile("cp.async.cg.shared.global [%0], [%1], 16;"
                 :: "r"(saddr), "l"(gaddr) : "memory");
}
#define CP_COMMIT()  asm volatile("cp.async.commit_group;" ::: "memory")
#define CP_WAIT0()   asm volatile("cp.async.wait_group 0;" ::: "memory")

#define RSTRIDE 80
#define T_AHI 0
#define T_ALO 10240
#define T_BHI 20480
#define T_BLO 30720
#define STAGE 40960
#define NSTAGE 2
#define CONV_SMEM (STAGE * NSTAGE)
#define NKSTEP 16           // K = 512 in chunks of 32

// ---------------- winograd-domain GEMM (bf16x3 mma.sync) --------------------
// grid (25 n-blocks, 4 co-blocks, 64 points), block 256, 2 CTAs/SM
__global__ __launch_bounds__(256, 2)
void wino_gemm() {
    extern __shared__ char dsm[];
    const uint32_t base = smem_u32(dsm);

    const int tid  = threadIdx.x;
    const int lane = tid & 31;
    const int wid  = tid >> 5;
    const int wm   = wid & 1;
    const int wn   = wid >> 1;
    const int n0   = blockIdx.x * 128;
    const int co0  = blockIdx.y * 128;
    const int p    = blockIdx.z;

    const int r0 = tid >> 2;
    const int q  = tid & 3;

    auto issue = [&](int j) {
        const int c0 = j << 5;
        const uint32_t sb = base + (j & 1) * STAGE;
#pragma unroll
        for (int e = 0; e < 2; e++) {
            const int row = r0 + 64 * e;
            const uint32_t co_ = (uint32_t)(row * RSTRIDE + q * 16);
            const size_t gA = ((size_t)p * COUT + co0 + row) * CIN + c0 + q * 8;
            cp16(sb + T_AHI + co_, g_uhi + gA);
            cp16(sb + T_ALO + co_, g_ulo + gA);
            const size_t gB = ((size_t)p * NTPAD + n0 + row) * CIN + c0 + q * 8;
            cp16(sb + T_BHI + co_, g_vhi + gB);
            cp16(sb + T_BLO + co_, g_vlo + gB);
        }
    };

    float acc[4][4][4];
#pragma unroll
    for (int mi = 0; mi < 4; mi++)
#pragma unroll
        for (int ni = 0; ni < 4; ni++)
#pragma unroll
            for (int r = 0; r < 4; r++) acc[mi][ni][r] = 0.f;

    issue(0); CP_COMMIT();

    // fragment address pieces
    // A: 16 rows (m) x k16 via x4;  B: two n8 tiles x k16 via one x4
    const uint32_t aRow  = (uint32_t)((wm * 64 + (lane & 15)) * RSTRIDE)
                         + (uint32_t)((lane >> 4) * 16);
    const uint32_t bRow4 = (uint32_t)((wn * 32 + (lane & 7) + (lane >> 4) * 8) * RSTRIDE)
                         + (uint32_t)(((lane >> 3) & 1) * 16);

    for (int i = 0; i < NKSTEP; i++) {
        CP_WAIT0();
        __syncthreads();
        if (i + 1 < NKSTEP) issue(i + 1);
        CP_COMMIT();

        const uint32_t sb = base + (i & 1) * STAGE;
#pragma unroll
        for (int kk = 0; kk < 2; kk++) {
            const uint32_t kByte = (uint32_t)(kk * 32);
            unsigned ah[4][4], al[4][4], bh[2][4], bl[2][4];
#pragma unroll
            for (int mi = 0; mi < 4; mi++) {
                uint32_t ad = sb + aRow + (uint32_t)(mi * 16 * RSTRIDE) + kByte;
                ldsm_x4(ah[mi], ad + T_AHI);
                ldsm_x4(al[mi], ad + T_ALO);
            }
#pragma unroll
            for (int nip = 0; nip < 2; nip++) {
                uint32_t bd = sb + bRow4 + (uint32_t)(nip * 16 * RSTRIDE) + kByte;
                ldsm_x4(bh[nip], bd + T_BHI);
                ldsm_x4(bl[nip], bd + T_BLO);
            }
            // pass 1: hi * hi  (16 independent MMAs)
#pragma unroll
            for (int mi = 0; mi < 4; mi++)
#pragma unroll
                for (int nip = 0; nip < 2; nip++) {
                    mma16816(acc[mi][2 * nip],     ah[mi], &bh[nip][0]);
                    mma16816(acc[mi][2 * nip + 1], ah[mi], &bh[nip][2]);
                }
            // pass 2: hi * lo
#pragma unroll
            for (int mi = 0; mi < 4; mi++)
#pragma unroll
                for (int nip = 0; nip < 2; nip++) {
                    mma16816(acc[mi][2 * nip],     ah[mi], &bl[nip][0]);
                    mma16816(acc[mi][2 * nip + 1], ah[mi], &bl[nip][2]);
                }
            // pass 3: lo * hi
#pragma unroll
            for (int mi = 0; mi < 4; mi++)
#pragma unroll
                for (int nip = 0; nip < 2; nip++) {
                    mma16816(acc[mi][2 * nip],     al[mi], &bh[nip][0]);
                    mma16816(acc[mi][2 * nip + 1], al[mi], &bh[nip][2]);
                }
        }
    }

    // epilogue: raw fp32 -> g_m[p][co][n]
#pragma unroll
    for (int mi = 0; mi < 4; mi++) {
        const int row0 = co0 + wm * 64 + mi * 16 + (lane >> 2);
        const int row1 = row0 + 8;
#pragma unroll
        for (int ni = 0; ni < 4; ni++) {
            const int col = n0 + wn * 32 + ni * 8 + (lane & 3) * 2;
            float2 o0 = make_float2(acc[mi][ni][0], acc[mi][ni][1]);
            float2 o1 = make_float2(acc[mi][ni][2], acc[mi][ni][3]);
            *(float2*)&g_m[((size_t)p * COUT + row0) * NTPAD + col] = o0;
            *(float2*)&g_m[((size_t)p * COUT + row1) * NTPAD + col] = o1;
        }
    }
}

// ---------------- inverse transform + bias + relu ---------------------------
// grid (98, 64), block 256: warp -> co, lane -> n
__global__ __launch_bounds__(256, 1)
void wino_out(const float* __restrict__ bias) {
    const int lane = threadIdx.x & 31;
    const int n  = blockIdx.x * 32 + lane;
    const int co = blockIdx.y * 8 + (threadIdx.x >> 5);

    float m[64];
    {
        size_t o = (size_t)co * NTPAD + n;
        const size_t stride = (size_t)COUT * NTPAD;
#pragma unroll
        for (int pp = 0; pp < 64; pp++) {
            m[pp] = g_m[o];
            o += stride;
        }
    }
    // A^T along t: 64 -> 32
    float z[32];
#pragma unroll
    for (int i = 0; i < 16; i++) {
        float m0 = m[i], m1 = m[16 + i], m2 = m[32 + i], m3 = m[48 + i];
        z[i]      = m0 + m1 + m2;
        z[16 + i] = m1 - m2 - m3;
    }
    // A^T along h: 32 -> 16
    float y2[16];
#pragma unroll
    for (int a = 0; a < 2; a++)
#pragma unroll
        for (int dw = 0; dw < 4; dw++) {
            int i0 = a * 16 + dw;
            float m0 = z[i0], m1 = z[i0 + 4], m2 = z[i0 + 8], m3 = z[i0 + 12];
            y2[a * 8 + dw]     = m0 + m1 + m2;
            y2[a * 8 + 4 + dw] = m1 - m2 - m3;
        }
    // A^T along w: 16 -> 8
    float out[8];
#pragma unroll
    for (int a = 0; a < 2; a++)
#pragma unroll
        for (int b2 = 0; b2 < 2; b2++) {
            int i0 = a * 8 + b2 * 4;
            out[a * 4 + b2 * 2 + 0] = y2[i0] + y2[i0 + 1] + y2[i0 + 2];
            out[a * 4 + b2 * 2 + 1] = y2[i0 + 1] - y2[i0 + 2] - y2[i0 + 3];
        }

    const float bv = bias[co];
    int b  = n / TPB;
    int r  = n - b * TPB;
    int tT = r / 196;
    int r2 = r - tT * 196;
    int tH = r2 / 14;
    int tW = r2 - tH * 14;
    int t = 2 * tT, h = 2 * tH, w = 2 * tW;
    float* dst = g_xbuf + ((size_t)b * CIN + co) * THW;
#pragma unroll
    for (int dt = 0; dt < 2; dt++)
#pragma unroll
        for (int dh = 0; dh < 2; dh++) {
            float2 v;
            v.x = fmaxf(out[dt * 4 + dh * 2 + 0] + bv, 0.f);
            v.y = fmaxf(out[dt * 4 + dh * 2 + 1] + bv, 0.f);
            *(float2*)&dst[(t + dt) * HWSZ + (h + dh) * WIDTH + w] = v;
        }
}

// ---------------- temporal max pools ----------------------------------------
__global__ void pool_kernel() {
    int idx = blockIdx.x * 256 + threadIdx.x;
    if (idx >= NB * CIN * HWSZ) return;
    int hw = idx % HWSZ;
    int bc = idx / HWSZ;
    const float* p = &g_xbuf[(size_t)bc * THW + hw];
    float v[16];
#pragma unroll
    for (int t = 0; t < 16; t++) v[t] = p[t * HWSZ];

    float m = v[0];
#pragma unroll
    for (int t = 1; t < 16; t++) m = fmaxf(m, v[t]);
    g_p16[(size_t)bc * HWSZ + hw] = m;

#pragma unroll
    for (int tp = 0; tp < 5; tp++) {
        float qv = v[tp];
#pragma unroll
        for (int d = 1; d < 12; d++) qv = fmaxf(qv, v[tp + d]);
        g_p12[((size_t)bc * 5 + tp) * HWSZ + hw] = qv;
    }
#pragma unroll
    for (int tp = 0; tp < 9; tp++) {
        float qv = v[tp];
#pragma unroll
        for (int d = 1; d < 8; d++) qv = fmaxf(qv, v[tp + d]);
        g_p8[((size_t)bc * 9 + tp) * HWSZ + hw] = qv;
    }
#pragma unroll
    for (int tp = 0; tp < 13; tp++) {
        float qv = v[tp];
#pragma unroll
        for (int d = 1; d < 4; d++) qv = fmaxf(qv, v[tp + d]);
        g_p4[((size_t)bc * 13 + tp) * HWSZ + hw] = qv;
    }
}

// ---------------- 1x1x1 head GEMM (packed f32x2) ----------------------------
__global__ __launch_bounds__(256)
void head_gemm(int pool_id, const float* __restrict__ Wh, const float* __restrict__ bh,
               float* __restrict__ dst, int O, int Tp, int mode) {
    const float* pool = pool_id == 0 ? g_p16 : pool_id == 1 ? g_p12
                       : pool_id == 2 ? g_p8 : g_p4;
    const int Tp784 = Tp * HWSZ;
    const int N = NB * Tp784;

    __shared__ __align__(16) float As[8][64];
    __shared__ __align__(16) float Bs[8][128];

    const int tid = threadIdx.x;
    const int s0  = blockIdx.x * 128;
    const int o0  = blockIdx.y * 64;
    const int ty  = tid >> 4;
    const int tx  = tid & 15;

    const int oL = o0 + (tid >> 2);
    const int cL = (tid & 3) * 2;

    int baseS[4], okS[4];
#pragma unroll
    for (int i = 0; i < 4; i++) {
        int idx = tid + 256 * i;
        int sn = idx & 127;
        int ss = s0 + sn;
        okS[i] = ss < N;
        int b = ss >= Tp784 ? 1 : 0;
        int r = ss - b * Tp784;
        baseS[i] = b * (CIN * Tp784) + r;
    }

    unsigned long long acc2[4][4];
#pragma unroll
    for (int m = 0; m < 4; m++)
#pragma unroll
        for (int j = 0; j < 4; j++) acc2[m][j] = 0ull;

    for (int c0 = 0; c0 < CIN; c0 += 8) {
        float a0 = 0.f, a1 = 0.f;
        if (oL < O) {
            a0 = Wh[oL * CIN + c0 + cL];
            a1 = Wh[oL * CIN + c0 + cL + 1];
        }
        As[cL][oL - o0]     = a0;
        As[cL + 1][oL - o0] = a1;
#pragma unroll
        for (int i = 0; i < 4; i++) {
            int idx = tid + 256 * i;
            int kk = idx >> 7, sn = idx & 127;
            float v = 0.f;
            if (okS[i]) v = pool[baseS[i] + (c0 + kk) * Tp784];
            Bs[kk][sn] = v;
        }
        __syncthreads();
#pragma unroll
        for (int kk = 0; kk < 8; kk++) {
            float4 a = *(const float4*)&As[kk][ty * 4];
            float av[4] = {a.x, a.y, a.z, a.w};
            ulonglong2 u0 = *(const ulonglong2*)&Bs[kk][tx * 8];
            ulonglong2 u1 = *(const ulonglong2*)&Bs[kk][tx * 8 + 4];
            unsigned long long bd[4] = {u0.x, u0.y, u1.x, u1.y};
#pragma unroll
            for (int m = 0; m < 4; m++) {
                unsigned long long ad;
                asm("mov.b64 %0, {%1, %1};" : "=l"(ad) : "r"(__float_as_uint(av[m])));
#pragma unroll
                for (int j = 0; j < 4; j++)
                    asm("fma.rn.f32x2 %0, %1, %2, %0;"
                        : "+l"(acc2[m][j]) : "l"(ad), "l"(bd[j]));
            }
        }
        __syncthreads();
    }

#pragma unroll
    for (int m = 0; m < 4; m++) {
        int o = o0 + ty * 4 + m;
        if (o >= O) continue;
        float bv = bh[o];
#pragma unroll
        for (int j = 0; j < 4; j++) {
            float2 v = *reinterpret_cast<float2*>(&acc2[m][j]);
#pragma unroll
            for (int e = 0; e < 2; e++) {
                int ss = s0 + tx * 8 + 2 * j + e;
                if (ss >= N) continue;
                float r = (e ? v.y : v.x) + bv;
                if (mode == 0) {
                    g_cls[o * N + ss] = r;
                } else {
                    int b  = ss >= Tp784 ? 1 : 0;
                    int rr = ss - b * Tp784;
                    dst[(size_t)b * O * Tp784 + (size_t)o * Tp784 + rr] = r;
                }
            }
        }
    }
}

// ---------------- paired softmax over channels (c, c+15) --------------------
__global__ void softmax_kernel(float* __restrict__ out, int Tp) {
    const int Tp784 = Tp * HWSZ;
    const int N = NB * Tp784;
    int idx = blockIdx.x * 256 + threadIdx.x;
    if (idx >= 15 * N) return;
    int c = idx / N;
    int ss = idx - c * N;
    float v0 = g_cls[c * N + ss];
    float v1 = g_cls[(c + 15) * N + ss];
    float mx = fmaxf(v0, v1);
    float e0 = expf(v0 - mx), e1 = expf(v1 - mx);
    float inv = 1.f / (e0 + e1);
    int b = ss >= Tp784 ? 1 : 0;
    int r = ss - b * Tp784;
    out[(size_t)b * 30 * Tp784 + (size_t)c * Tp784 + r]        = e0 * inv;
    out[(size_t)b * 30 * Tp784 + (size_t)(c + 15) * Tp784 + r] = e1 * inv;
}

// ---------------- launch -----------------------------------------------------
extern "C" void kernel_launch(void* const* d_in, const int* in_sizes, int n_in,
                              void* d_out, int out_size) {
    const float* base  = (const float*)d_in[0];
    const float* Wc    = (const float*)d_in[4];
    const float* bc    = (const float*)d_in[5];
    const float* Wcls  = (const float*)d_in[6];
    const float* bcls  = (const float*)d_in[7];
    const float* Wbb[4] = {(const float*)d_in[8],  (const float*)d_in[10],
                           (const float*)d_in[12], (const float*)d_in[14]};
    const float* bbb[4] = {(const float*)d_in[9],  (const float*)d_in[11],
                           (const float*)d_in[13], (const float*)d_in[15]};
    float* out = (float*)d_out;

    cudaFuncSetAttribute(wino_gemm, cudaFuncAttributeMaxDynamicSharedMemorySize,
                         CONV_SMEM);

    wino_w<<<(COUT * CIN + 255) / 256, 256>>>(Wc);
    prep_xt<<<dim3(THW / 32, CIN / 32, NB), dim3(32, 8)>>>(base);
    wino_x<<<dim3(NTPAD, 2), 256>>>();
    wino_gemm<<<dim3(NTPAD / 128, COUT / 128, NPTS), 256, CONV_SMEM>>>();
    wino_out<<<dim3(NTILE / 32, COUT / 8), 256>>>(bc);
    pool_kernel<<<(NB * CIN * HWSZ + 255) / 256, 256>>>();

    const int TpA[4] = {1, 5, 9, 13};
    const int Obb[4] = {960, 720, 480, 240};
    const long probOff[4] = {0, 47040, 282240, 705600};
    const long bboxOff[4] = {1317120, 2822400, 8467200, 15240960};

    for (int p = 0; p < 4; p++) {
        int Tp = TpA[p];
        int N = NB * Tp * HWSZ;
        int gx = (N + 127) / 128;
        head_gemm<<<dim3(gx, 1), 256>>>(p, Wcls, bcls, out, 30, Tp, 0);
        softmax_kernel<<<(15 * N + 255) / 256, 256>>>(out + probOff[p], Tp);
        int gy = (Obb[p] + 63) / 64;
        head_gemm<<<dim3(gx, gy), 256>>>(p, Wbb[p], bbb[p], out + bboxOff[p],
                                         Obb[p], Tp, 1);
    }
}

// round 6
// speedup vs baseline: 6.6256x; 1.6994x over previous
#include <cuda_runtime.h>
#include <cuda_bf16.h>
#include <cstdint>
#include <math.h>

#define CIN   512
#define COUT  512
#define T_IN  16
#define HWSZ  784           // 28*28
#define THW   12544         // 16*784
#define NB    2
#define WIDTH 28

#define NTILE   3136        // 2 * 8 * 14 * 14 winograd tiles
#define NTPAD   3200        // padded to 25 * 128
#define TPB     1568        // tiles per batch
#define NPTS    64          // 4*4*4 transform points

#define NPOOLS_S 43904      // 1568 + 7840 + 14112 + 20384
#define NPOOLS_PAD 44032    // +128 guard rows
#define WROWS   2430        // 30 + 960 + 720 + 480 + 240
#define WROWS_PAD 2560

// ---------------- scratch (device globals; no allocations allowed) ----------
__device__ float g_xbuf[NB * CIN * THW];               // conv output (relu'd)
__device__ float g_xt[NB * THW * CIN];                 // x transposed [s][c] fp32
__device__ __nv_bfloat16 g_uhi[NPTS * COUT * CIN];     // weights  [p][co][ci]
__device__ __nv_bfloat16 g_ulo[NPTS * COUT * CIN];
__device__ __nv_bfloat16 g_vhi[(size_t)NPTS * NTPAD * CIN];  // acts [p][n][ci]
__device__ __nv_bfloat16 g_vlo[(size_t)NPTS * NTPAD * CIN];
__device__ float g_m[(size_t)NPTS * COUT * NTPAD];     // gemm out [p][co][n]
__device__ float g_p16[NB * CIN * 1  * HWSZ];
__device__ float g_p12[NB * CIN * 5  * HWSZ];
__device__ float g_p8 [NB * CIN * 9  * HWSZ];
__device__ float g_p4 [NB * CIN * 13 * HWSZ];
__device__ __nv_bfloat16 g_phi[(size_t)NPOOLS_PAD * CIN];  // pools [s][c] hi
__device__ __nv_bfloat16 g_plo[(size_t)NPOOLS_PAD * CIN];
__device__ __nv_bfloat16 g_whh[WROWS_PAD * CIN];       // head weights hi
__device__ __nv_bfloat16 g_whl[WROWS_PAD * CIN];
__device__ float g_cls[30 * NPOOLS_S];                 // cls scores, concat

// ---------------- job tables ------------------------------------------------
__constant__ int c_Tp784[4]   = {784, 3920, 7056, 10192};
__constant__ int c_N[4]       = {1568, 7840, 14112, 20384};
__constant__ int c_poolOff[4] = {0, 1568, 9408, 23520};
__constant__ int c_clsOff[4]  = {0, 47040, 282240, 705600};
__constant__ long c_bboxOff[4]= {1317120, 2822400, 8467200, 15240960};
// 8 jobs: 4 cls then 4 bbox
__constant__ int c_jp[8]    = {0, 1, 2, 3, 0, 1, 2, 3};
__constant__ int c_jO[8]    = {30, 30, 30, 30, 960, 720, 480, 240};
__constant__ int c_jgx[8]   = {13, 62, 111, 160, 13, 62, 111, 160};
__constant__ int c_jstart[9]= {0, 13, 75, 186, 346, 541, 1285, 2173, 2813};
__constant__ int c_jwOff[8] = {0, 0, 0, 0, 30, 990, 1710, 2190};

// ---------------- weight transform: [co][ci][27] -> U[p][co][ci] hi/lo ------
__global__ void wino_w(const float* __restrict__ w) {
    int idx = blockIdx.x * 256 + threadIdx.x;
    if (idx >= COUT * CIN) return;
    int ci = idx & 511;
    int co = idx >> 9;
    float g[27];
#pragma unroll
    for (int k = 0; k < 27; k++) g[k] = w[(size_t)idx * 27 + k];

    float u1[4][9];
#pragma unroll
    for (int i = 0; i < 9; i++) {
        float c0 = g[i], c1 = g[9 + i], c2 = g[18 + i];
        u1[0][i] = c0;
        u1[1][i] = 0.5f * (c0 + c1 + c2);
        u1[2][i] = 0.5f * (c0 - c1 + c2);
        u1[3][i] = c2;
    }
    float u2[4][4][3];
#pragma unroll
    for (int a = 0; a < 4; a++)
#pragma unroll
        for (int kw = 0; kw < 3; kw++) {
            float c0 = u1[a][kw], c1 = u1[a][3 + kw], c2 = u1[a][6 + kw];
            u2[a][0][kw] = c0;
            u2[a][1][kw] = 0.5f * (c0 + c1 + c2);
            u2[a][2][kw] = 0.5f * (c0 - c1 + c2);
            u2[a][3][kw] = c2;
        }
#pragma unroll
    for (int a = 0; a < 4; a++)
#pragma unroll
        for (int bh = 0; bh < 4; bh++) {
            float c0 = u2[a][bh][0], c1 = u2[a][bh][1], c2 = u2[a][bh][2];
            float uw[4];
            uw[0] = c0;
            uw[1] = 0.5f * (c0 + c1 + c2);
            uw[2] = 0.5f * (c0 - c1 + c2);
            uw[3] = c2;
#pragma unroll
            for (int cw = 0; cw < 4; cw++) {
                int p = a * 16 + bh * 4 + cw;
                float v = uw[cw];
                __nv_bfloat16 hi = __float2bfloat16_rn(v);
                float rem = v - __bfloat162float(hi);
                size_t o = ((size_t)p * COUT + co) * CIN + ci;
                g_uhi[o] = hi;
                g_ulo[o] = __float2bfloat16_rn(rem);
            }
        }
}

// ---------------- x [b][c][thw] -> [b*thw][c] fp32 transpose ----------------
__global__ void prep_xt(const float* __restrict__ x) {
    __shared__ float tile[32][33];
    int b  = blockIdx.z;
    int s0 = blockIdx.x * 32;
    int c0 = blockIdx.y * 32;
    for (int i = threadIdx.y; i < 32; i += 8)
        tile[i][threadIdx.x] = x[((size_t)b * CIN + c0 + i) * THW + s0 + threadIdx.x];
    __syncthreads();
    for (int i = threadIdx.y; i < 32; i += 8)
        g_xt[((size_t)b * THW + s0 + i) * CIN + c0 + threadIdx.x] = tile[threadIdx.x][i];
}

// ---------------- input transform: V[p][n][ci] hi/lo ------------------------
__global__ __launch_bounds__(256, 1)
void wino_x() {
    const int n  = blockIdx.x;
    const int ci = blockIdx.y * 256 + threadIdx.x;
    float d[64];
    if (n < NTILE) {
        int b  = n / TPB;
        int r  = n - b * TPB;
        int tT = r / 196;
        int r2 = r - tT * 196;
        int tH = r2 / 14;
        int tW = r2 - tH * 14;
        int t0 = 2 * tT - 1, h0 = 2 * tH - 1, w0 = 2 * tW - 1;
#pragma unroll
        for (int dt = 0; dt < 4; dt++) {
            int t = t0 + dt;
#pragma unroll
            for (int dh = 0; dh < 4; dh++) {
                int h = h0 + dh;
#pragma unroll
                for (int dw = 0; dw < 4; dw++) {
                    int w = w0 + dw;
                    int ok = ((unsigned)t < (unsigned)T_IN) & ((unsigned)h < 28u) &
                             ((unsigned)w < 28u);
                    float v = 0.f;
                    if (ok)
                        v = g_xt[((size_t)b * THW + t * HWSZ + h * WIDTH + w) * CIN + ci];
                    d[dt * 16 + dh * 4 + dw] = v;
                }
            }
        }
    } else {
#pragma unroll
        for (int k = 0; k < 64; k++) d[k] = 0.f;
    }
    // B^T along w
#pragma unroll
    for (int i = 0; i < 16; i++) {
        float a0 = d[i * 4 + 0], a1 = d[i * 4 + 1], a2 = d[i * 4 + 2], a3 = d[i * 4 + 3];
        d[i * 4 + 0] = a0 - a2;
        d[i * 4 + 1] = a1 + a2;
        d[i * 4 + 2] = a2 - a1;
        d[i * 4 + 3] = a1 - a3;
    }
    // B^T along h
#pragma unroll
    for (int dt = 0; dt < 4; dt++)
#pragma unroll
        for (int dw = 0; dw < 4; dw++) {
            int i0 = dt * 16 + dw;
            float a0 = d[i0], a1 = d[i0 + 4], a2 = d[i0 + 8], a3 = d[i0 + 12];
            d[i0]      = a0 - a2;
            d[i0 + 4]  = a1 + a2;
            d[i0 + 8]  = a2 - a1;
            d[i0 + 12] = a1 - a3;
        }
    // B^T along t
#pragma unroll
    for (int i = 0; i < 16; i++) {
        float a0 = d[i], a1 = d[i + 16], a2 = d[i + 32], a3 = d[i + 48];
        d[i]      = a0 - a2;
        d[i + 16] = a1 + a2;
        d[i + 32] = a2 - a1;
        d[i + 48] = a1 - a3;
    }
    size_t o = ((size_t)n) * CIN + ci;
    const size_t stride = (size_t)NTPAD * CIN;
#pragma unroll
    for (int p = 0; p < 64; p++) {
        float v = d[p];
        __nv_bfloat16 hi = __float2bfloat16_rn(v);
        float rem = v - __bfloat162float(hi);
        g_vhi[o] = hi;
        g_vlo[o] = __float2bfloat16_rn(rem);
        o += stride;
    }
}

// ================= mma.sync helpers =========================================
__device__ __forceinline__ uint32_t smem_u32(const void* p) {
    uint32_t a;
    asm("{ .reg .u64 t; cvta.to.shared.u64 t, %1; cvt.u32.u64 %0, t; }"
        : "=r"(a) : "l"(p));
    return a;
}
__device__ __forceinline__ void ldsm_x4(unsigned* r, uint32_t addr) {
    asm volatile("ldmatrix.sync.aligned.m8n8.x4.shared.b16 {%0,%1,%2,%3}, [%4];"
                 : "=r"(r[0]), "=r"(r[1]), "=r"(r[2]), "=r"(r[3]) : "r"(addr));
}
__device__ __forceinline__ void mma16816(float* d, const unsigned* a, const unsigned* b) {
    asm volatile(
        "mma.sync.aligned.m16n8k16.row.col.f32.bf16.bf16.f32 "
        "{%0,%1,%2,%3}, {%4,%5,%6,%7}, {%8,%9}, {%0,%1,%2,%3};"
        : "+f"(d[0]), "+f"(d[1]), "+f"(d[2]), "+f"(d[3])
        : "r"(a[0]), "r"(a[1]), "r"(a[2]), "r"(a[3]), "r"(b[0]), "r"(b[1]));
}
__device__ __forceinline__ void cp16(uint32_t saddr, const void* gaddr) {
    asm volatile("cp.async.cg.shared.global [%0], [%1], 16;"
                 :: "r"(saddr), "l"(gaddr) : "memory");
}
#define CP_COMMIT()  asm volatile("cp.async.commit_group;" ::: "memory")
#define CP_WAIT0()   asm volatile("cp.async.wait_group 0;" ::: "memory")

#define RSTRIDE 80
#define T_AHI 0
#define T_ALO 10240
#define T_BHI 20480
#define T_BLO 30720
#define STAGE 40960
#define CONV_SMEM (STAGE * 2)
#define NKSTEP 16           // K = 512 in chunks of 32

// ---------------- winograd-domain GEMM (bf16x3 mma.sync) --------------------
__global__ __launch_bounds__(256, 2)
void wino_gemm() {
    extern __shared__ char dsm[];
    const uint32_t base = smem_u32(dsm);

    const int tid  = threadIdx.x;
    const int lane = tid & 31;
    const int wid  = tid >> 5;
    const int wm   = wid & 1;
    const int wn   = wid >> 1;
    const int n0   = blockIdx.x * 128;
    const int co0  = blockIdx.y * 128;
    const int p    = blockIdx.z;

    const int r0 = tid >> 2;
    const int q  = tid & 3;

    auto issue = [&](int j) {
        const int c0 = j << 5;
        const uint32_t sb = base + (j & 1) * STAGE;
#pragma unroll
        for (int e = 0; e < 2; e++) {
            const int row = r0 + 64 * e;
            const uint32_t co_ = (uint32_t)(row * RSTRIDE + q * 16);
            const size_t gA = ((size_t)p * COUT + co0 + row) * CIN + c0 + q * 8;
            cp16(sb + T_AHI + co_, g_uhi + gA);
            cp16(sb + T_ALO + co_, g_ulo + gA);
            const size_t gB = ((size_t)p * NTPAD + n0 + row) * CIN + c0 + q * 8;
            cp16(sb + T_BHI + co_, g_vhi + gB);
            cp16(sb + T_BLO + co_, g_vlo + gB);
        }
    };

    float acc[4][4][4];
#pragma unroll
    for (int mi = 0; mi < 4; mi++)
#pragma unroll
        for (int ni = 0; ni < 4; ni++)
#pragma unroll
            for (int r = 0; r < 4; r++) acc[mi][ni][r] = 0.f;

    issue(0); CP_COMMIT();

    const uint32_t aRow  = (uint32_t)((wm * 64 + (lane & 15)) * RSTRIDE)
                         + (uint32_t)((lane >> 4) * 16);
    const uint32_t bRow4 = (uint32_t)((wn * 32 + (lane & 7) + (lane >> 4) * 8) * RSTRIDE)
                         + (uint32_t)(((lane >> 3) & 1) * 16);

    for (int i = 0; i < NKSTEP; i++) {
        CP_WAIT0();
        __syncthreads();
        if (i + 1 < NKSTEP) issue(i + 1);
        CP_COMMIT();

        const uint32_t sb = base + (i & 1) * STAGE;
#pragma unroll
        for (int kk = 0; kk < 2; kk++) {
            const uint32_t kByte = (uint32_t)(kk * 32);
            unsigned ah[4][4], al[4][4], bh[2][4], bl[2][4];
#pragma unroll
            for (int mi = 0; mi < 4; mi++) {
                uint32_t ad = sb + aRow + (uint32_t)(mi * 16 * RSTRIDE) + kByte;
                ldsm_x4(ah[mi], ad + T_AHI);
                ldsm_x4(al[mi], ad + T_ALO);
            }
#pragma unroll
            for (int nip = 0; nip < 2; nip++) {
                uint32_t bd = sb + bRow4 + (uint32_t)(nip * 16 * RSTRIDE) + kByte;
                ldsm_x4(bh[nip], bd + T_BHI);
                ldsm_x4(bl[nip], bd + T_BLO);
            }
#pragma unroll
            for (int mi = 0; mi < 4; mi++)
#pragma unroll
                for (int nip = 0; nip < 2; nip++) {
                    mma16816(acc[mi][2 * nip],     ah[mi], &bh[nip][0]);
                    mma16816(acc[mi][2 * nip + 1], ah[mi], &bh[nip][2]);
                }
#pragma unroll
            for (int mi = 0; mi < 4; mi++)
#pragma unroll
                for (int nip = 0; nip < 2; nip++) {
                    mma16816(acc[mi][2 * nip],     ah[mi], &bl[nip][0]);
                    mma16816(acc[mi][2 * nip + 1], ah[mi], &bl[nip][2]);
                }
#pragma unroll
            for (int mi = 0; mi < 4; mi++)
#pragma unroll
                for (int nip = 0; nip < 2; nip++) {
                    mma16816(acc[mi][2 * nip],     al[mi], &bh[nip][0]);
                    mma16816(acc[mi][2 * nip + 1], al[mi], &bh[nip][2]);
                }
        }
    }

#pragma unroll
    for (int mi = 0; mi < 4; mi++) {
        const int row0 = co0 + wm * 64 + mi * 16 + (lane >> 2);
        const int row1 = row0 + 8;
#pragma unroll
        for (int ni = 0; ni < 4; ni++) {
            const int col = n0 + wn * 32 + ni * 8 + (lane & 3) * 2;
            float2 o0 = make_float2(acc[mi][ni][0], acc[mi][ni][1]);
            float2 o1 = make_float2(acc[mi][ni][2], acc[mi][ni][3]);
            *(float2*)&g_m[((size_t)p * COUT + row0) * NTPAD + col] = o0;
            *(float2*)&g_m[((size_t)p * COUT + row1) * NTPAD + col] = o1;
        }
    }
}

// ---------------- inverse transform + bias + relu ---------------------------
__global__ __launch_bounds__(256, 1)
void wino_out(const float* __restrict__ bias) {
    const int lane = threadIdx.x & 31;
    const int n  = blockIdx.x * 32 + lane;
    const int co = blockIdx.y * 8 + (threadIdx.x >> 5);

    float m[64];
    {
        size_t o = (size_t)co * NTPAD + n;
        const size_t stride = (size_t)COUT * NTPAD;
#pragma unroll
        for (int pp = 0; pp < 64; pp++) {
            m[pp] = g_m[o];
            o += stride;
        }
    }
    float z[32];
#pragma unroll
    for (int i = 0; i < 16; i++) {
        float m0 = m[i], m1 = m[16 + i], m2 = m[32 + i], m3 = m[48 + i];
        z[i]      = m0 + m1 + m2;
        z[16 + i] = m1 - m2 - m3;
    }
    float y2[16];
#pragma unroll
    for (int a = 0; a < 2; a++)
#pragma unroll
        for (int dw = 0; dw < 4; dw++) {
            int i0 = a * 16 + dw;
            float m0 = z[i0], m1 = z[i0 + 4], m2 = z[i0 + 8], m3 = z[i0 + 12];
            y2[a * 8 + dw]     = m0 + m1 + m2;
            y2[a * 8 + 4 + dw] = m1 - m2 - m3;
        }
    float out[8];
#pragma unroll
    for (int a = 0; a < 2; a++)
#pragma unroll
        for (int b2 = 0; b2 < 2; b2++) {
            int i0 = a * 8 + b2 * 4;
            out[a * 4 + b2 * 2 + 0] = y2[i0] + y2[i0 + 1] + y2[i0 + 2];
            out[a * 4 + b2 * 2 + 1] = y2[i0 + 1] - y2[i0 + 2] - y2[i0 + 3];
        }

    const float bv = bias[co];
    int b  = n / TPB;
    int r  = n - b * TPB;
    int tT = r / 196;
    int r2 = r - tT * 196;
    int tH = r2 / 14;
    int tW = r2 - tH * 14;
    int t = 2 * tT, h = 2 * tH, w = 2 * tW;
    float* dst = g_xbuf + ((size_t)b * CIN + co) * THW;
#pragma unroll
    for (int dt = 0; dt < 2; dt++)
#pragma unroll
        for (int dh = 0; dh < 2; dh++) {
            float2 v;
            v.x = fmaxf(out[dt * 4 + dh * 2 + 0] + bv, 0.f);
            v.y = fmaxf(out[dt * 4 + dh * 2 + 1] + bv, 0.f);
            *(float2*)&dst[(t + dt) * HWSZ + (h + dh) * WIDTH + w] = v;
        }
}

// ---------------- temporal max pools ----------------------------------------
__global__ void pool_kernel() {
    int idx = blockIdx.x * 256 + threadIdx.x;
    if (idx >= NB * CIN * HWSZ) return;
    int hw = idx % HWSZ;
    int bc = idx / HWSZ;
    const float* p = &g_xbuf[(size_t)bc * THW + hw];
    float v[16];
#pragma unroll
    for (int t = 0; t < 16; t++) v[t] = p[t * HWSZ];

    float m = v[0];
#pragma unroll
    for (int t = 1; t < 16; t++) m = fmaxf(m, v[t]);
    g_p16[(size_t)bc * HWSZ + hw] = m;

#pragma unroll
    for (int tp = 0; tp < 5; tp++) {
        float qv = v[tp];
#pragma unroll
        for (int d = 1; d < 12; d++) qv = fmaxf(qv, v[tp + d]);
        g_p12[((size_t)bc * 5 + tp) * HWSZ + hw] = qv;
    }
#pragma unroll
    for (int tp = 0; tp < 9; tp++) {
        float qv = v[tp];
#pragma unroll
        for (int d = 1; d < 8; d++) qv = fmaxf(qv, v[tp + d]);
        g_p8[((size_t)bc * 9 + tp) * HWSZ + hw] = qv;
    }
#pragma unroll
    for (int tp = 0; tp < 13; tp++) {
        float qv = v[tp];
#pragma unroll
        for (int d = 1; d < 4; d++) qv = fmaxf(qv, v[tp + d]);
        g_p4[((size_t)bc * 13 + tp) * HWSZ + hw] = qv;
    }
}

// ---------------- pool transpose + bf16 hi/lo: [b][c][r] -> [s][c] ----------
// grid (319, 16, 8): z = p*2+b, x = r-tile/32, y = c-tile/32
__global__ void pool_tr() {
    __shared__ float tile[32][33];
    const int z = blockIdx.z;
    const int p = z >> 1;
    const int b = z & 1;
    const int T784 = c_Tp784[p];
    const int r0 = blockIdx.x * 32;
    if (r0 >= T784) return;
    const int c0 = blockIdx.y * 32;
    const float* src = (p == 0 ? g_p16 : p == 1 ? g_p12 : p == 2 ? g_p8 : g_p4)
                     + (size_t)b * CIN * T784;
    for (int i = threadIdx.y; i < 32; i += 8) {
        int r = r0 + threadIdx.x;
        tile[i][threadIdx.x] = (r < T784) ? src[(size_t)(c0 + i) * T784 + r] : 0.f;
    }
    __syncthreads();
    const int sBase = c_poolOff[p] + b * T784;
    for (int i = threadIdx.y; i < 32; i += 8) {
        int r = r0 + i;
        if (r < T784) {
            float v = tile[threadIdx.x][i];
            __nv_bfloat16 hi = __float2bfloat16_rn(v);
            float rem = v - __bfloat162float(hi);
            size_t o = (size_t)(sBase + r) * CIN + c0 + threadIdx.x;
            g_phi[o] = hi;
            g_plo[o] = __float2bfloat16_rn(rem);
        }
    }
}

// ---------------- head weight convert: concat rows, bf16 hi/lo --------------
__global__ void prep_wh(const float* __restrict__ Wcls, const float* __restrict__ W0,
                        const float* __restrict__ W1, const float* __restrict__ W2,
                        const float* __restrict__ W3) {
    int idx = blockIdx.x * 256 + threadIdx.x;
    if (idx >= WROWS * CIN) return;
    int c   = idx & 511;
    int row = idx >> 9;
    const float* src;
    int lr;
    if (row < 30)        { src = Wcls; lr = row; }
    else if (row < 990)  { src = W0;   lr = row - 30; }
    else if (row < 1710) { src = W1;   lr = row - 990; }
    else if (row < 2190) { src = W2;   lr = row - 1710; }
    else                 { src = W3;   lr = row - 2190; }
    float v = src[(size_t)lr * CIN + c];
    __nv_bfloat16 hi = __float2bfloat16_rn(v);
    float rem = v - __bfloat162float(hi);
    g_whh[idx] = hi;
    g_whl[idx] = __float2bfloat16_rn(rem);
}

// ---------------- batched head GEMM (bf16x3 mma.sync) -----------------------
// BM=64 (o), BN=128 (s), BK=32, all 8 jobs in one launch (2813 blocks)
#define H_AHI 0
#define H_ALO 5120
#define H_BHI 10240
#define H_BLO 20480
#define HSTAGE 30720
#define HEAD_SMEM (HSTAGE * 2)

__global__ __launch_bounds__(256, 2)
void head_mma(float* __restrict__ dout,
              const float* __restrict__ bcls, const float* __restrict__ b0,
              const float* __restrict__ b1,   const float* __restrict__ b2,
              const float* __restrict__ b3) {
    extern __shared__ char dsm[];
    const uint32_t base = smem_u32(dsm);

    // resolve job
    int j = 0;
#pragma unroll
    for (int t = 1; t < 8; t++)
        if ((int)blockIdx.x >= c_jstart[t]) j = t;
    const int p     = c_jp[j];
    const int O     = c_jO[j];
    const int gx    = c_jgx[j];
    const int local = blockIdx.x - c_jstart[j];
    const int by    = local / gx;
    const int bx    = local - by * gx;
    const int s0    = bx * 128;
    const int o0    = by * 64;
    const int wOff  = c_jwOff[j];
    const int N     = c_N[p];
    const int T784  = c_Tp784[p];
    const int sGlob = c_poolOff[p] + s0;

    const int tid  = threadIdx.x;
    const int lane = tid & 31;
    const int wid  = tid >> 5;
    const int wm   = wid & 1;         // 0..1 -> 32 o rows each
    const int wn   = wid >> 1;        // 0..3 -> 32 s cols each

    auto issue = [&](int i) {
        const int c0 = i << 5;
        const uint32_t sb = base + (i & 1) * HSTAGE;
        // A: 64 rows x 32 c; 256 threads -> 1 chunk each
        {
            const int row = tid >> 2;
            const int q   = tid & 3;
            const uint32_t so = (uint32_t)(row * RSTRIDE + q * 8 * 2);
            const size_t gA = (size_t)(wOff + o0 + row) * CIN + c0 + q * 8;
            cp16(sb + H_AHI + so, g_whh + gA);
            cp16(sb + H_ALO + so, g_whl + gA);
        }
        // B: 128 rows x 32 c; 256 threads -> 2 chunks each
        {
            const int row = tid >> 1;
            const int q0  = (tid & 1) * 2;
#pragma unroll
            for (int e = 0; e < 2; e++) {
                const int q = q0 + e;
                const uint32_t so = (uint32_t)(row * RSTRIDE + q * 16);
                const size_t gB = (size_t)(sGlob + row) * CIN + c0 + q * 8;
                cp16(sb + H_BHI + so, g_phi + gB);
                cp16(sb + H_BLO + so, g_plo + gB);
            }
        }
    };

    float acc[2][4][4];
#pragma unroll
    for (int mi = 0; mi < 2; mi++)
#pragma unroll
        for (int ni = 0; ni < 4; ni++)
#pragma unroll
            for (int r = 0; r < 4; r++) acc[mi][ni][r] = 0.f;

    issue(0); CP_COMMIT();

    const uint32_t aRow  = (uint32_t)((wm * 32 + (lane & 15)) * RSTRIDE)
                         + (uint32_t)((lane >> 4) * 16);
    const uint32_t bRow4 = (uint32_t)((wn * 32 + (lane & 7) + (lane >> 4) * 8) * RSTRIDE)
                         + (uint32_t)(((lane >> 3) & 1) * 16);

    for (int i = 0; i < NKSTEP; i++) {
        CP_WAIT0();
        __syncthreads();
        if (i + 1 < NKSTEP) issue(i + 1);
        CP_COMMIT();

        const uint32_t sb = base + (i & 1) * HSTAGE;
#pragma unroll
        for (int kk = 0; kk < 2; kk++) {
            const uint32_t kByte = (uint32_t)(kk * 32);
            unsigned ah[2][4], al[2][4], bh[2][4], bl[2][4];
#pragma unroll
            for (int mi = 0; mi < 2; mi++) {
                uint32_t ad = sb + aRow + (uint32_t)(mi * 16 * RSTRIDE) + kByte;
                ldsm_x4(ah[mi], ad + H_AHI);
                ldsm_x4(al[mi], ad + H_ALO);
            }
#pragma unroll
            for (int nip = 0; nip < 2; nip++) {
                uint32_t bd = sb + bRow4 + (uint32_t)(nip * 16 * RSTRIDE) + kByte;
                ldsm_x4(bh[nip], bd + H_BHI);
                ldsm_x4(bl[nip], bd + H_BLO);
            }
#pragma unroll
            for (int mi = 0; mi < 2; mi++)
#pragma unroll
                for (int nip = 0; nip < 2; nip++) {
                    mma16816(acc[mi][2 * nip],     ah[mi], &bh[nip][0]);
                    mma16816(acc[mi][2 * nip + 1], ah[mi], &bh[nip][2]);
                }
#pragma unroll
            for (int mi = 0; mi < 2; mi++)
#pragma unroll
                for (int nip = 0; nip < 2; nip++) {
                    mma16816(acc[mi][2 * nip],     ah[mi], &bl[nip][0]);
                    mma16816(acc[mi][2 * nip + 1], ah[mi], &bl[nip][2]);
                }
#pragma unroll
            for (int mi = 0; mi < 2; mi++)
#pragma unroll
                for (int nip = 0; nip < 2; nip++) {
                    mma16816(acc[mi][2 * nip],     al[mi], &bh[nip][0]);
                    mma16816(acc[mi][2 * nip + 1], al[mi], &bh[nip][2]);
                }
        }
    }

    // epilogue
    const float* bias = j == 0 || j < 4
        ? (j < 4 ? bcls : bcls)
        : bcls;
    // proper bias select:
    const float* bptr = (j < 4) ? bcls : (j == 4 ? b0 : j == 5 ? b1 : j == 6 ? b2 : b3);

#pragma unroll
    for (int mi = 0; mi < 2; mi++) {
#pragma unroll
        for (int half = 0; half < 2; half++) {
            const int o = o0 + wm * 32 + mi * 16 + half * 8 + (lane >> 2);
            if (o >= O) continue;
            const float bv = bptr[o];
#pragma unroll
            for (int ni = 0; ni < 4; ni++) {
#pragma unroll
                for (int e = 0; e < 2; e++) {
                    const int s = s0 + wn * 32 + ni * 8 + (lane & 3) * 2 + e;
                    if (s >= N) continue;
                    const float r = acc[mi][ni][half * 2 + e] + bv;
                    if (j < 4) {
                        g_cls[c_clsOff[p] + o * N + s] = r;
                    } else {
                        const int bb = s >= T784 ? 1 : 0;
                        const int rr = s - bb * T784;
                        dout[c_bboxOff[p] + (size_t)bb * O * T784 +
                             (size_t)o * T784 + rr] = r;
                    }
                }
            }
        }
    }
    (void)bias;
}

// ---------------- combined softmax over all pools ---------------------------
__global__ void softmax_all(float* __restrict__ out) {
    int idx = blockIdx.x * 256 + threadIdx.x;
    // ranges: 15*N cumulative {0, 23520, 141120, 352800, 658560}
    if (idx >= 658560) return;
    int p, local;
    if (idx < 23520)        { p = 0; local = idx; }
    else if (idx < 141120)  { p = 1; local = idx - 23520; }
    else if (idx < 352800)  { p = 2; local = idx - 141120; }
    else                    { p = 3; local = idx - 352800; }
    const int N = c_N[p];
    const int T784 = c_Tp784[p];
    int c  = local / N;
    int ss = local - c * N;
    const float* cls = g_cls + c_clsOff[p];
    float v0 = cls[c * N + ss];
    float v1 = cls[(c + 15) * N + ss];
    float mx = fmaxf(v0, v1);
    float e0 = expf(v0 - mx), e1 = expf(v1 - mx);
    float inv = 1.f / (e0 + e1);
    int b = ss >= T784 ? 1 : 0;
    int r = ss - b * T784;
    long po = (p == 0) ? 0L : (p == 1) ? 47040L : (p == 2) ? 282240L : 705600L;
    out[po + (size_t)b * 30 * T784 + (size_t)c * T784 + r]        = e0 * inv;
    out[po + (size_t)b * 30 * T784 + (size_t)(c + 15) * T784 + r] = e1 * inv;
}

// ---------------- launch -----------------------------------------------------
extern "C" void kernel_launch(void* const* d_in, const int* in_sizes, int n_in,
                              void* d_out, int out_size) {
    const float* base  = (const float*)d_in[0];
    const float* Wc    = (const float*)d_in[4];
    const float* bc    = (const float*)d_in[5];
    const float* Wcls  = (const float*)d_in[6];
    const float* bcls  = (const float*)d_in[7];
    const float* Wbb[4] = {(const float*)d_in[8],  (const float*)d_in[10],
                           (const float*)d_in[12], (const float*)d_in[14]};
    const float* bbb[4] = {(const float*)d_in[9],  (const float*)d_in[11],
                           (const float*)d_in[13], (const float*)d_in[15]};
    float* out = (float*)d_out;

    cudaFuncSetAttribute(wino_gemm, cudaFuncAttributeMaxDynamicSharedMemorySize,
                         CONV_SMEM);
    cudaFuncSetAttribute(head_mma, cudaFuncAttributeMaxDynamicSharedMemorySize,
                         HEAD_SMEM);

    wino_w<<<(COUT * CIN + 255) / 256, 256>>>(Wc);
    prep_wh<<<(WROWS * CIN + 255) / 256, 256>>>(Wcls, Wbb[0], Wbb[1], Wbb[2], Wbb[3]);
    prep_xt<<<dim3(THW / 32, CIN / 32, NB), dim3(32, 8)>>>(base);
    wino_x<<<dim3(NTPAD, 2), 256>>>();
    wino_gemm<<<dim3(NTPAD / 128, COUT / 128, NPTS), 256, CONV_SMEM>>>();
    wino_out<<<dim3(NTILE / 32, COUT / 8), 256>>>(bc);
    pool_kernel<<<(NB * CIN * HWSZ + 255) / 256, 256>>>();
    pool_tr<<<dim3(319, 16, 8), dim3(32, 8)>>>();
    head_mma<<<2813, 256, HEAD_SMEM>>>(out, bcls, bbb[0], bbb[1], bbb[2], bbb[3]);
    softmax_all<<<(658560 + 255) / 256, 256>>>(out);
}

// round 7
// speedup vs baseline: 8.5747x; 1.2942x over previous
#include <cuda_runtime.h>
#include <cuda_bf16.h>
#include <cuda_fp16.h>
#include <cstdint>
#include <math.h>

#define CIN   512
#define COUT  512
#define T_IN  16
#define HWSZ  784           // 28*28
#define THW   12544         // 16*784
#define NB    2
#define WIDTH 28

#define NTILE   3136        // 2 * 8 * 14 * 14 winograd tiles
#define NTPAD   3200        // padded to 25 * 128
#define TPB     1568        // tiles per batch
#define NPTS    64          // 4*4*4 transform points

#define NPOOLS_S 43904      // 1568 + 7840 + 14112 + 20384
#define NPOOLS_PAD 44032
#define WROWS   2430        // 30 + 960 + 720 + 480 + 240
#define WROWS_PAD 2560

// ---------------- scratch (device globals; no allocations allowed) ----------
__device__ float g_xbuf[NB * CIN * THW];               // conv output (relu'd)
__device__ float g_xt[NB * THW * CIN];                 // x transposed [s][c] fp32
__device__ __half g_uh[NPTS * COUT * CIN];             // weights hi [p][co][ci]
__device__ __half g_ul[NPTS * COUT * CIN];             // weights lo
__device__ __half g_vh[(size_t)NPTS * NTPAD * CIN];    // acts fp16 [p][n][ci]
__device__ float g_m[(size_t)NPTS * COUT * NTPAD];     // gemm out [p][co][n]
__device__ float g_p16[NB * CIN * 1  * HWSZ];
__device__ float g_p12[NB * CIN * 5  * HWSZ];
__device__ float g_p8 [NB * CIN * 9  * HWSZ];
__device__ float g_p4 [NB * CIN * 13 * HWSZ];
__device__ __half g_ph[(size_t)NPOOLS_PAD * CIN];      // pools fp16 [s][c]
__device__ __half g_whh[WROWS_PAD * CIN];              // head weights hi
__device__ __half g_whl[WROWS_PAD * CIN];              // head weights lo
__device__ float g_cls[30 * NPOOLS_S];                 // cls scores, concat

// ---------------- job tables ------------------------------------------------
__constant__ int c_Tp784[4]   = {784, 3920, 7056, 10192};
__constant__ int c_N[4]       = {1568, 7840, 14112, 20384};
__constant__ int c_poolOff[4] = {0, 1568, 9408, 23520};
__constant__ int c_clsOff[4]  = {0, 47040, 282240, 705600};
__constant__ long c_bboxOff[4]= {1317120, 2822400, 8467200, 15240960};
__constant__ int c_jp[8]    = {0, 1, 2, 3, 0, 1, 2, 3};
__constant__ int c_jO[8]    = {30, 30, 30, 30, 960, 720, 480, 240};
__constant__ int c_jgx[8]   = {13, 62, 111, 160, 13, 62, 111, 160};
__constant__ int c_jstart[9]= {0, 13, 75, 186, 346, 541, 1285, 2173, 2813};
__constant__ int c_jwOff[8] = {0, 0, 0, 0, 30, 990, 1710, 2190};

// ---------------- weight transform: [co][ci][27] -> U[p][co][ci] fp16 hi/lo -
__global__ void wino_w(const float* __restrict__ w) {
    int idx = blockIdx.x * 256 + threadIdx.x;
    if (idx >= COUT * CIN) return;
    int ci = idx & 511;
    int co = idx >> 9;
    float g[27];
#pragma unroll
    for (int k = 0; k < 27; k++) g[k] = w[(size_t)idx * 27 + k];

    float u1[4][9];
#pragma unroll
    for (int i = 0; i < 9; i++) {
        float c0 = g[i], c1 = g[9 + i], c2 = g[18 + i];
        u1[0][i] = c0;
        u1[1][i] = 0.5f * (c0 + c1 + c2);
        u1[2][i] = 0.5f * (c0 - c1 + c2);
        u1[3][i] = c2;
    }
    float u2[4][4][3];
#pragma unroll
    for (int a = 0; a < 4; a++)
#pragma unroll
        for (int kw = 0; kw < 3; kw++) {
            float c0 = u1[a][kw], c1 = u1[a][3 + kw], c2 = u1[a][6 + kw];
            u2[a][0][kw] = c0;
            u2[a][1][kw] = 0.5f * (c0 + c1 + c2);
            u2[a][2][kw] = 0.5f * (c0 - c1 + c2);
            u2[a][3][kw] = c2;
        }
#pragma unroll
    for (int a = 0; a < 4; a++)
#pragma unroll
        for (int bh = 0; bh < 4; bh++) {
            float c0 = u2[a][bh][0], c1 = u2[a][bh][1], c2 = u2[a][bh][2];
            float uw[4];
            uw[0] = c0;
            uw[1] = 0.5f * (c0 + c1 + c2);
            uw[2] = 0.5f * (c0 - c1 + c2);
            uw[3] = c2;
#pragma unroll
            for (int cw = 0; cw < 4; cw++) {
                int p = a * 16 + bh * 4 + cw;
                float v = uw[cw];
                __half hi = __float2half_rn(v);
                float rem = v - __half2float(hi);
                size_t o = ((size_t)p * COUT + co) * CIN + ci;
                g_uh[o] = hi;
                g_ul[o] = __float2half_rn(rem);
            }
        }
}

// ---------------- x [b][c][thw] -> [b*thw][c] fp32 transpose ----------------
__global__ void prep_xt(const float* __restrict__ x) {
    __shared__ float tile[32][33];
    int b  = blockIdx.z;
    int s0 = blockIdx.x * 32;
    int c0 = blockIdx.y * 32;
    for (int i = threadIdx.y; i < 32; i += 8)
        tile[i][threadIdx.x] = x[((size_t)b * CIN + c0 + i) * THW + s0 + threadIdx.x];
    __syncthreads();
    for (int i = threadIdx.y; i < 32; i += 8)
        g_xt[((size_t)b * THW + s0 + i) * CIN + c0 + threadIdx.x] = tile[threadIdx.x][i];
}

// ---------------- input transform: V[p][n][ci] fp16 -------------------------
__global__ __launch_bounds__(256, 1)
void wino_x() {
    const int n  = blockIdx.x;
    const int ci = blockIdx.y * 256 + threadIdx.x;
    float d[64];
    if (n < NTILE) {
        int b  = n / TPB;
        int r  = n - b * TPB;
        int tT = r / 196;
        int r2 = r - tT * 196;
        int tH = r2 / 14;
        int tW = r2 - tH * 14;
        int t0 = 2 * tT - 1, h0 = 2 * tH - 1, w0 = 2 * tW - 1;
#pragma unroll
        for (int dt = 0; dt < 4; dt++) {
            int t = t0 + dt;
#pragma unroll
            for (int dh = 0; dh < 4; dh++) {
                int h = h0 + dh;
#pragma unroll
                for (int dw = 0; dw < 4; dw++) {
                    int w = w0 + dw;
                    int ok = ((unsigned)t < (unsigned)T_IN) & ((unsigned)h < 28u) &
                             ((unsigned)w < 28u);
                    float v = 0.f;
                    if (ok)
                        v = g_xt[((size_t)b * THW + t * HWSZ + h * WIDTH + w) * CIN + ci];
                    d[dt * 16 + dh * 4 + dw] = v;
                }
            }
        }
    } else {
#pragma unroll
        for (int k = 0; k < 64; k++) d[k] = 0.f;
    }
    // B^T along w
#pragma unroll
    for (int i = 0; i < 16; i++) {
        float a0 = d[i * 4 + 0], a1 = d[i * 4 + 1], a2 = d[i * 4 + 2], a3 = d[i * 4 + 3];
        d[i * 4 + 0] = a0 - a2;
        d[i * 4 + 1] = a1 + a2;
        d[i * 4 + 2] = a2 - a1;
        d[i * 4 + 3] = a1 - a3;
    }
    // B^T along h
#pragma unroll
    for (int dt = 0; dt < 4; dt++)
#pragma unroll
        for (int dw = 0; dw < 4; dw++) {
            int i0 = dt * 16 + dw;
            float a0 = d[i0], a1 = d[i0 + 4], a2 = d[i0 + 8], a3 = d[i0 + 12];
            d[i0]      = a0 - a2;
            d[i0 + 4]  = a1 + a2;
            d[i0 + 8]  = a2 - a1;
            d[i0 + 12] = a1 - a3;
        }
    // B^T along t
#pragma unroll
    for (int i = 0; i < 16; i++) {
        float a0 = d[i], a1 = d[i + 16], a2 = d[i + 32], a3 = d[i + 48];
        d[i]      = a0 - a2;
        d[i + 16] = a1 + a2;
        d[i + 32] = a2 - a1;
        d[i + 48] = a1 - a3;
    }
    size_t o = ((size_t)n) * CIN + ci;
    const size_t stride = (size_t)NTPAD * CIN;
#pragma unroll
    for (int p = 0; p < 64; p++) {
        g_vh[o] = __float2half_rn(d[p]);
        o += stride;
    }
}

// ================= mma.sync helpers =========================================
__device__ __forceinline__ uint32_t smem_u32(const void* p) {
    uint32_t a;
    asm("{ .reg .u64 t; cvta.to.shared.u64 t, %1; cvt.u32.u64 %0, t; }"
        : "=r"(a) : "l"(p));
    return a;
}
__device__ __forceinline__ void ldsm_x4(unsigned* r, uint32_t addr) {
    asm volatile("ldmatrix.sync.aligned.m8n8.x4.shared.b16 {%0,%1,%2,%3}, [%4];"
                 : "=r"(r[0]), "=r"(r[1]), "=r"(r[2]), "=r"(r[3]) : "r"(addr));
}
__device__ __forceinline__ void mma16816(float* d, const unsigned* a, const unsigned* b) {
    asm volatile(
        "mma.sync.aligned.m16n8k16.row.col.f32.f16.f16.f32 "
        "{%0,%1,%2,%3}, {%4,%5,%6,%7}, {%8,%9}, {%0,%1,%2,%3};"
        : "+f"(d[0]), "+f"(d[1]), "+f"(d[2]), "+f"(d[3])
        : "r"(a[0]), "r"(a[1]), "r"(a[2]), "r"(a[3]), "r"(b[0]), "r"(b[1]));
}
__device__ __forceinline__ void cp16(uint32_t saddr, const void* gaddr) {
    asm volatile("cp.async.cg.shared.global [%0], [%1], 16;"
                 :: "r"(saddr), "l"(gaddr) : "memory");
}
#define CP_COMMIT()  asm volatile("cp.async.commit_group;" ::: "memory")
#define CP_WAIT0()   asm volatile("cp.async.wait_group 0;" ::: "memory")

#define RSTRIDE 80
#define T_AH 0
#define T_AL 10240
#define T_BH 20480
#define STAGE 30720
#define CONV_SMEM (STAGE * 2)
#define NKSTEP 16           // K = 512 in chunks of 32

// ---------------- winograd-domain GEMM (fp16 A-split, mma.sync) -------------
__global__ __launch_bounds__(256, 2)
void wino_gemm() {
    extern __shared__ char dsm[];
    const uint32_t base = smem_u32(dsm);

    const int tid  = threadIdx.x;
    const int lane = tid & 31;
    const int wid  = tid >> 5;
    const int wm   = wid & 1;
    const int wn   = wid >> 1;
    const int n0   = blockIdx.x * 128;
    const int co0  = blockIdx.y * 128;
    const int p    = blockIdx.z;

    const int r0 = tid >> 1;          // 0..127
    const int cp = tid & 1;           // chunk pair

    auto issue = [&](int j) {
        const int c0 = j << 5;
        const uint32_t sb = base + (j & 1) * STAGE;
#pragma unroll
        for (int e = 0; e < 2; e++) {
            const int q = cp * 2 + e;
            const uint32_t so = (uint32_t)(r0 * RSTRIDE + q * 16);
            const size_t gA = ((size_t)p * COUT + co0 + r0) * CIN + c0 + q * 8;
            cp16(sb + T_AH + so, g_uh + gA);
            cp16(sb + T_AL + so, g_ul + gA);
            const size_t gB = ((size_t)p * NTPAD + n0 + r0) * CIN + c0 + q * 8;
            cp16(sb + T_BH + so, g_vh + gB);
        }
    };

    float acc[4][4][4];
#pragma unroll
    for (int mi = 0; mi < 4; mi++)
#pragma unroll
        for (int ni = 0; ni < 4; ni++)
#pragma unroll
            for (int r = 0; r < 4; r++) acc[mi][ni][r] = 0.f;

    issue(0); CP_COMMIT();

    const uint32_t aRow  = (uint32_t)((wm * 64 + (lane & 15)) * RSTRIDE)
                         + (uint32_t)((lane >> 4) * 16);
    const uint32_t bRow4 = (uint32_t)((wn * 32 + (lane & 7) + (lane >> 4) * 8) * RSTRIDE)
                         + (uint32_t)(((lane >> 3) & 1) * 16);

    for (int i = 0; i < NKSTEP; i++) {
        CP_WAIT0();
        __syncthreads();
        if (i + 1 < NKSTEP) issue(i + 1);
        CP_COMMIT();

        const uint32_t sb = base + (i & 1) * STAGE;
#pragma unroll
        for (int kk = 0; kk < 2; kk++) {
            const uint32_t kByte = (uint32_t)(kk * 32);
            unsigned ah[4][4], al[4][4], bh[2][4];
#pragma unroll
            for (int mi = 0; mi < 4; mi++) {
                uint32_t ad = sb + aRow + (uint32_t)(mi * 16 * RSTRIDE) + kByte;
                ldsm_x4(ah[mi], ad + T_AH);
                ldsm_x4(al[mi], ad + T_AL);
            }
#pragma unroll
            for (int nip = 0; nip < 2; nip++) {
                uint32_t bd = sb + bRow4 + (uint32_t)(nip * 16 * RSTRIDE) + kByte;
                ldsm_x4(bh[nip], bd + T_BH);
            }
#pragma unroll
            for (int mi = 0; mi < 4; mi++)
#pragma unroll
                for (int nip = 0; nip < 2; nip++) {
                    mma16816(acc[mi][2 * nip],     ah[mi], &bh[nip][0]);
                    mma16816(acc[mi][2 * nip + 1], ah[mi], &bh[nip][2]);
                }
#pragma unroll
            for (int mi = 0; mi < 4; mi++)
#pragma unroll
                for (int nip = 0; nip < 2; nip++) {
                    mma16816(acc[mi][2 * nip],     al[mi], &bh[nip][0]);
                    mma16816(acc[mi][2 * nip + 1], al[mi], &bh[nip][2]);
                }
        }
    }

#pragma unroll
    for (int mi = 0; mi < 4; mi++) {
        const int row0 = co0 + wm * 64 + mi * 16 + (lane >> 2);
        const int row1 = row0 + 8;
#pragma unroll
        for (int ni = 0; ni < 4; ni++) {
            const int col = n0 + wn * 32 + ni * 8 + (lane & 3) * 2;
            float2 o0 = make_float2(acc[mi][ni][0], acc[mi][ni][1]);
            float2 o1 = make_float2(acc[mi][ni][2], acc[mi][ni][3]);
            *(float2*)&g_m[((size_t)p * COUT + row0) * NTPAD + col] = o0;
            *(float2*)&g_m[((size_t)p * COUT + row1) * NTPAD + col] = o1;
        }
    }
}

// ---------------- inverse transform + bias + relu ---------------------------
__global__ __launch_bounds__(256, 1)
void wino_out(const float* __restrict__ bias) {
    const int lane = threadIdx.x & 31;
    const int n  = blockIdx.x * 32 + lane;
    const int co = blockIdx.y * 8 + (threadIdx.x >> 5);

    float m[64];
    {
        size_t o = (size_t)co * NTPAD + n;
        const size_t stride = (size_t)COUT * NTPAD;
#pragma unroll
        for (int pp = 0; pp < 64; pp++) {
            m[pp] = g_m[o];
            o += stride;
        }
    }
    float z[32];
#pragma unroll
    for (int i = 0; i < 16; i++) {
        float m0 = m[i], m1 = m[16 + i], m2 = m[32 + i], m3 = m[48 + i];
        z[i]      = m0 + m1 + m2;
        z[16 + i] = m1 - m2 - m3;
    }
    float y2[16];
#pragma unroll
    for (int a = 0; a < 2; a++)
#pragma unroll
        for (int dw = 0; dw < 4; dw++) {
            int i0 = a * 16 + dw;
            float m0 = z[i0], m1 = z[i0 + 4], m2 = z[i0 + 8], m3 = z[i0 + 12];
            y2[a * 8 + dw]     = m0 + m1 + m2;
            y2[a * 8 + 4 + dw] = m1 - m2 - m3;
        }
    float out[8];
#pragma unroll
    for (int a = 0; a < 2; a++)
#pragma unroll
        for (int b2 = 0; b2 < 2; b2++) {
            int i0 = a * 8 + b2 * 4;
            out[a * 4 + b2 * 2 + 0] = y2[i0] + y2[i0 + 1] + y2[i0 + 2];
            out[a * 4 + b2 * 2 + 1] = y2[i0 + 1] - y2[i0 + 2] - y2[i0 + 3];
        }

    const float bv = bias[co];
    int b  = n / TPB;
    int r  = n - b * TPB;
    int tT = r / 196;
    int r2 = r - tT * 196;
    int tH = r2 / 14;
    int tW = r2 - tH * 14;
    int t = 2 * tT, h = 2 * tH, w = 2 * tW;
    float* dst = g_xbuf + ((size_t)b * CIN + co) * THW;
#pragma unroll
    for (int dt = 0; dt < 2; dt++)
#pragma unroll
        for (int dh = 0; dh < 2; dh++) {
            float2 v;
            v.x = fmaxf(out[dt * 4 + dh * 2 + 0] + bv, 0.f);
            v.y = fmaxf(out[dt * 4 + dh * 2 + 1] + bv, 0.f);
            *(float2*)&dst[(t + dt) * HWSZ + (h + dh) * WIDTH + w] = v;
        }
}

// ---------------- temporal max pools ----------------------------------------
__global__ void pool_kernel() {
    int idx = blockIdx.x * 256 + threadIdx.x;
    if (idx >= NB * CIN * HWSZ) return;
    int hw = idx % HWSZ;
    int bc = idx / HWSZ;
    const float* p = &g_xbuf[(size_t)bc * THW + hw];
    float v[16];
#pragma unroll
    for (int t = 0; t < 16; t++) v[t] = p[t * HWSZ];

    float m = v[0];
#pragma unroll
    for (int t = 1; t < 16; t++) m = fmaxf(m, v[t]);
    g_p16[(size_t)bc * HWSZ + hw] = m;

#pragma unroll
    for (int tp = 0; tp < 5; tp++) {
        float qv = v[tp];
#pragma unroll
        for (int d = 1; d < 12; d++) qv = fmaxf(qv, v[tp + d]);
        g_p12[((size_t)bc * 5 + tp) * HWSZ + hw] = qv;
    }
#pragma unroll
    for (int tp = 0; tp < 9; tp++) {
        float qv = v[tp];
#pragma unroll
        for (int d = 1; d < 8; d++) qv = fmaxf(qv, v[tp + d]);
        g_p8[((size_t)bc * 9 + tp) * HWSZ + hw] = qv;
    }
#pragma unroll
    for (int tp = 0; tp < 13; tp++) {
        float qv = v[tp];
#pragma unroll
        for (int d = 1; d < 4; d++) qv = fmaxf(qv, v[tp + d]);
        g_p4[((size_t)bc * 13 + tp) * HWSZ + hw] = qv;
    }
}

// ---------------- pool transpose + fp16: [b][c][r] -> [s][c] ----------------
__global__ void pool_tr() {
    __shared__ float tile[32][33];
    const int z = blockIdx.z;
    const int p = z >> 1;
    const int b = z & 1;
    const int T784 = c_Tp784[p];
    const int r0 = blockIdx.x * 32;
    if (r0 >= T784) return;
    const int c0 = blockIdx.y * 32;
    const float* src = (p == 0 ? g_p16 : p == 1 ? g_p12 : p == 2 ? g_p8 : g_p4)
                     + (size_t)b * CIN * T784;
    for (int i = threadIdx.y; i < 32; i += 8) {
        int r = r0 + threadIdx.x;
        tile[i][threadIdx.x] = (r < T784) ? src[(size_t)(c0 + i) * T784 + r] : 0.f;
    }
    __syncthreads();
    const int sBase = c_poolOff[p] + b * T784;
    for (int i = threadIdx.y; i < 32; i += 8) {
        int r = r0 + i;
        if (r < T784)
            g_ph[(size_t)(sBase + r) * CIN + c0 + threadIdx.x] =
                __float2half_rn(tile[threadIdx.x][i]);
    }
}

// ---------------- head weight convert: concat rows, fp16 hi/lo --------------
__global__ void prep_wh(const float* __restrict__ Wcls, const float* __restrict__ W0,
                        const float* __restrict__ W1, const float* __restrict__ W2,
                        const float* __restrict__ W3) {
    int idx = blockIdx.x * 256 + threadIdx.x;
    if (idx >= WROWS * CIN) return;
    int c   = idx & 511;
    int row = idx >> 9;
    const float* src;
    int lr;
    if (row < 30)        { src = Wcls; lr = row; }
    else if (row < 990)  { src = W0;   lr = row - 30; }
    else if (row < 1710) { src = W1;   lr = row - 990; }
    else if (row < 2190) { src = W2;   lr = row - 1710; }
    else                 { src = W3;   lr = row - 2190; }
    float v = src[(size_t)lr * CIN + c];
    __half hi = __float2half_rn(v);
    float rem = v - __half2float(hi);
    g_whh[idx] = hi;
    g_whl[idx] = __float2half_rn(rem);
}

// ---------------- batched head GEMM (fp16 A-split, mma.sync) ----------------
#define H_AH 0
#define H_AL 5120
#define H_BH 10240
#define HSTAGE 20480
#define HEAD_SMEM (HSTAGE * 2)

__global__ __launch_bounds__(256, 2)
void head_mma(float* __restrict__ dout,
              const float* __restrict__ bcls, const float* __restrict__ b0,
              const float* __restrict__ b1,   const float* __restrict__ b2,
              const float* __restrict__ b3) {
    extern __shared__ char dsm[];
    const uint32_t base = smem_u32(dsm);

    int j = 0;
#pragma unroll
    for (int t = 1; t < 8; t++)
        if ((int)blockIdx.x >= c_jstart[t]) j = t;
    const int p     = c_jp[j];
    const int O     = c_jO[j];
    const int gx    = c_jgx[j];
    const int local = blockIdx.x - c_jstart[j];
    const int by    = local / gx;
    const int bx    = local - by * gx;
    const int s0    = bx * 128;
    const int o0    = by * 64;
    const int wOff  = c_jwOff[j];
    const int N     = c_N[p];
    const int T784  = c_Tp784[p];
    const int sGlob = c_poolOff[p] + s0;

    const int tid  = threadIdx.x;
    const int lane = tid & 31;
    const int wid  = tid >> 5;
    const int wm   = wid & 1;
    const int wn   = wid >> 1;

    auto issue = [&](int i) {
        const int c0 = i << 5;
        const uint32_t sb = base + (i & 1) * HSTAGE;
        // A: 64 rows x 4 chunks -> 1 chunk/thread (hi + lo)
        {
            const int row = tid >> 2;
            const int q   = tid & 3;
            const uint32_t so = (uint32_t)(row * RSTRIDE + q * 16);
            const size_t gA = (size_t)(wOff + o0 + row) * CIN + c0 + q * 8;
            cp16(sb + H_AH + so, g_whh + gA);
            cp16(sb + H_AL + so, g_whl + gA);
        }
        // B: 128 rows x 4 chunks -> 2 chunks/thread
        {
            const int row = tid >> 1;
            const int q0  = (tid & 1) * 2;
#pragma unroll
            for (int e = 0; e < 2; e++) {
                const int q = q0 + e;
                const uint32_t so = (uint32_t)(row * RSTRIDE + q * 16);
                const size_t gB = (size_t)(sGlob + row) * CIN + c0 + q * 8;
                cp16(sb + H_BH + so, g_ph + gB);
            }
        }
    };

    float acc[2][4][4];
#pragma unroll
    for (int mi = 0; mi < 2; mi++)
#pragma unroll
        for (int ni = 0; ni < 4; ni++)
#pragma unroll
            for (int r = 0; r < 4; r++) acc[mi][ni][r] = 0.f;

    issue(0); CP_COMMIT();

    const uint32_t aRow  = (uint32_t)((wm * 32 + (lane & 15)) * RSTRIDE)
                         + (uint32_t)((lane >> 4) * 16);
    const uint32_t bRow4 = (uint32_t)((wn * 32 + (lane & 7) + (lane >> 4) * 8) * RSTRIDE)
                         + (uint32_t)(((lane >> 3) & 1) * 16);

    for (int i = 0; i < NKSTEP; i++) {
        CP_WAIT0();
        __syncthreads();
        if (i + 1 < NKSTEP) issue(i + 1);
        CP_COMMIT();

        const uint32_t sb = base + (i & 1) * HSTAGE;
#pragma unroll
        for (int kk = 0; kk < 2; kk++) {
            const uint32_t kByte = (uint32_t)(kk * 32);
            unsigned ah[2][4], al[2][4], bh[2][4];
#pragma unroll
            for (int mi = 0; mi < 2; mi++) {
                uint32_t ad = sb + aRow + (uint32_t)(mi * 16 * RSTRIDE) + kByte;
                ldsm_x4(ah[mi], ad + H_AH);
                ldsm_x4(al[mi], ad + H_AL);
            }
#pragma unroll
            for (int nip = 0; nip < 2; nip++) {
                uint32_t bd = sb + bRow4 + (uint32_t)(nip * 16 * RSTRIDE) + kByte;
                ldsm_x4(bh[nip], bd + H_BH);
            }
#pragma unroll
            for (int mi = 0; mi < 2; mi++)
#pragma unroll
                for (int nip = 0; nip < 2; nip++) {
                    mma16816(acc[mi][2 * nip],     ah[mi], &bh[nip][0]);
                    mma16816(acc[mi][2 * nip + 1], ah[mi], &bh[nip][2]);
                }
#pragma unroll
            for (int mi = 0; mi < 2; mi++)
#pragma unroll
                for (int nip = 0; nip < 2; nip++) {
                    mma16816(acc[mi][2 * nip],     al[mi], &bh[nip][0]);
                    mma16816(acc[mi][2 * nip + 1], al[mi], &bh[nip][2]);
                }
        }
    }

    const float* bptr = (j < 4) ? bcls : (j == 4 ? b0 : j == 5 ? b1 : j == 6 ? b2 : b3);

#pragma unroll
    for (int mi = 0; mi < 2; mi++) {
#pragma unroll
        for (int half = 0; half < 2; half++) {
            const int o = o0 + wm * 32 + mi * 16 + half * 8 + (lane >> 2);
            if (o >= O) continue;
            const float bv = bptr[o];
#pragma unroll
            for (int ni = 0; ni < 4; ni++) {
#pragma unroll
                for (int e = 0; e < 2; e++) {
                    const int s = s0 + wn * 32 + ni * 8 + (lane & 3) * 2 + e;
                    if (s >= N) continue;
                    const float r = acc[mi][ni][half * 2 + e] + bv;
                    if (j < 4) {
                        g_cls[c_clsOff[p] + o * N + s] = r;
                    } else {
                        const int bb = s >= T784 ? 1 : 0;
                        const int rr = s - bb * T784;
                        dout[c_bboxOff[p] + (size_t)bb * O * T784 +
                             (size_t)o * T784 + rr] = r;
                    }
                }
            }
        }
    }
}

// ---------------- combined softmax over all pools ---------------------------
__global__ void softmax_all(float* __restrict__ out) {
    int idx = blockIdx.x * 256 + threadIdx.x;
    if (idx >= 658560) return;
    int p, local;
    if (idx < 23520)        { p = 0; local = idx; }
    else if (idx < 141120)  { p = 1; local = idx - 23520; }
    else if (idx < 352800)  { p = 2; local = idx - 141120; }
    else                    { p = 3; local = idx - 352800; }
    const int N = c_N[p];
    const int T784 = c_Tp784[p];
    int c  = local / N;
    int ss = local - c * N;
    const float* cls = g_cls + c_clsOff[p];
    float v0 = cls[c * N + ss];
    float v1 = cls[(c + 15) * N + ss];
    float mx = fmaxf(v0, v1);
    float e0 = expf(v0 - mx), e1 = expf(v1 - mx);
    float inv = 1.f / (e0 + e1);
    int b = ss >= T784 ? 1 : 0;
    int r = ss - b * T784;
    long po = (p == 0) ? 0L : (p == 1) ? 47040L : (p == 2) ? 282240L : 705600L;
    out[po + (size_t)b * 30 * T784 + (size_t)c * T784 + r]        = e0 * inv;
    out[po + (size_t)b * 30 * T784 + (size_t)(c + 15) * T784 + r] = e1 * inv;
}

// ---------------- launch -----------------------------------------------------
extern "C" void kernel_launch(void* const* d_in, const int* in_sizes, int n_in,
                              void* d_out, int out_size) {
    const float* base  = (const float*)d_in[0];
    const float* Wc    = (const float*)d_in[4];
    const float* bc    = (const float*)d_in[5];
    const float* Wcls  = (const float*)d_in[6];
    const float* bcls  = (const float*)d_in[7];
    const float* Wbb[4] = {(const float*)d_in[8],  (const float*)d_in[10],
                           (const float*)d_in[12], (const float*)d_in[14]};
    const float* bbb[4] = {(const float*)d_in[9],  (const float*)d_in[11],
                           (const float*)d_in[13], (const float*)d_in[15]};
    float* out = (float*)d_out;

    cudaFuncSetAttribute(wino_gemm, cudaFuncAttributeMaxDynamicSharedMemorySize,
                         CONV_SMEM);
    cudaFuncSetAttribute(head_mma, cudaFuncAttributeMaxDynamicSharedMemorySize,
                         HEAD_SMEM);

    wino_w<<<(COUT * CIN + 255) / 256, 256>>>(Wc);
    prep_wh<<<(WROWS * CIN + 255) / 256, 256>>>(Wcls, Wbb[0], Wbb[1], Wbb[2], Wbb[3]);
    prep_xt<<<dim3(THW / 32, CIN / 32, NB), dim3(32, 8)>>>(base);
    wino_x<<<dim3(NTPAD, 2), 256>>>();
    wino_gemm<<<dim3(NTPAD / 128, COUT / 128, NPTS), 256, CONV_SMEM>>>();
    wino_out<<<dim3(NTILE / 32, COUT / 8), 256>>>(bc);
    pool_kernel<<<(NB * CIN * HWSZ + 255) / 256, 256>>>();
    pool_tr<<<dim3(319, 16, 8), dim3(32, 8)>>>();
    head_mma<<<2813, 256, HEAD_SMEM>>>(out, bcls, bbb[0], bbb[1], bbb[2], bbb[3]);
    softmax_all<<<(658560 + 255) / 256, 256>>>(out);
}